// round 3
// baseline (speedup 1.0000x reference)
#include <cuda_runtime.h>
#include <math.h>

// Problem constants
#define B_    4
#define NTOK  1568
#define C_    512
#define NH    8
#define HD    64
#define M_ALL (B_*NTOK)   // 6272

// One big scratch buffer: 10 planes of [6272, 512] floats = 128.45 MB
__device__ float g_scratch[10ull * M_ALL * C_];

// ---------------------------------------------------------------------------
// Tokenize: x [B, C, N] -> t [B, N, C]  (N = T*H*W = 1568)
// ---------------------------------------------------------------------------
__global__ void tok_kernel(const float* __restrict__ x, float* __restrict__ t) {
    __shared__ float tile[32][33];
    int b = blockIdx.z;
    int n0 = blockIdx.x * 32;
    int c0 = blockIdx.y * 32;
    const float* xb = x + (size_t)b * C_ * NTOK;
    float* tb = t + (size_t)b * NTOK * C_;
    int tx = threadIdx.x, ty = threadIdx.y;   // 32 x 8
    #pragma unroll
    for (int i = ty; i < 32; i += 8) {
        int c = c0 + i, n = n0 + tx;
        tile[i][tx] = xb[(size_t)c * NTOK + n];
    }
    __syncthreads();
    #pragma unroll
    for (int i = ty; i < 32; i += 8) {
        int n = n0 + i, c = c0 + tx;
        tb[(size_t)n * C_ + c] = tile[tx][i];
    }
}

// ---------------------------------------------------------------------------
// LayerNorm over last dim (512). One block of 128 threads per token row.
// ---------------------------------------------------------------------------
__global__ void ln_kernel(const float* __restrict__ X, const float* __restrict__ g,
                          const float* __restrict__ bt, float* __restrict__ Y) {
    int row = blockIdx.x;
    const float* x = X + (size_t)row * C_;
    float* y = Y + (size_t)row * C_;
    int tid = threadIdx.x;
    int lane = tid & 31, wid = tid >> 5;

    float4 v = *(const float4*)(x + tid * 4);
    float s  = v.x + v.y + v.z + v.w;
    float s2 = v.x*v.x + v.y*v.y + v.z*v.z + v.w*v.w;

    #pragma unroll
    for (int off = 16; off; off >>= 1) {
        s  += __shfl_xor_sync(0xffffffffu, s,  off);
        s2 += __shfl_xor_sync(0xffffffffu, s2, off);
    }
    __shared__ float smS[4], smS2[4];
    __shared__ float mu_s, rs_s;
    if (lane == 0) { smS[wid] = s; smS2[wid] = s2; }
    __syncthreads();
    if (tid == 0) {
        float S1 = smS[0] + smS[1] + smS[2] + smS[3];
        float S2 = smS2[0] + smS2[1] + smS2[2] + smS2[3];
        float mu = S1 * (1.f / C_);
        float var = S2 * (1.f / C_) - mu * mu;
        mu_s = mu;
        rs_s = rsqrtf(var + 1e-5f);
    }
    __syncthreads();
    float mu = mu_s, rs = rs_s;
    float4 gv = *(const float4*)(g  + tid * 4);
    float4 bv = *(const float4*)(bt + tid * 4);
    float4 o;
    o.x = (v.x - mu) * rs * gv.x + bv.x;
    o.y = (v.y - mu) * rs * gv.y + bv.y;
    o.z = (v.z - mu) * rs * gv.z + bv.z;
    o.w = (v.w - mu) * rs * gv.w + bv.w;
    *(float4*)(y + tid * 4) = o;
}

// ---------------------------------------------------------------------------
// SGEMM: C[M,N] = A[M,K] @ B[N,K]^T + bias[N]
// M=6272, N=512, K=512. 128x128 tiles, K-tile 16, double-buffered smem,
// 256 threads, 8x8 micro-tiles.
// mode 0: plain row-major store C[m*N+n]
// mode 1: output head: relu(v)*rsqrt(1+eps)*bn_g[n]+bn_b[n],
//         stored transposed per batch: out[(b*N + n)*1568 + tok]
// ---------------------------------------------------------------------------
__global__ __launch_bounds__(256) void gemm_kernel(
    const float* __restrict__ A, const float* __restrict__ Bw,
    const float* __restrict__ bias, float* __restrict__ Cc,
    int mode, const float* __restrict__ bn_g, const float* __restrict__ bn_b)
{
    const int N = 512, K = 512;
    __shared__ float As[2][16][132];
    __shared__ float Bs[2][16][132];
    int tid = threadIdx.x;
    int bm = blockIdx.y * 128;
    int bn = blockIdx.x * 128;

    // Global loaders: each thread loads rows lr and lr+64, 4 consecutive cols
    int lr = tid >> 2;             // 0..63
    int lc = (tid & 3) << 2;       // 0,4,8,12
    const float* Ap = A  + (size_t)(bm + lr) * K + lc;
    const float* Bp = Bw + (size_t)(bn + lr) * K + lc;

    int tm = (tid >> 4) * 8;
    int tn = (tid & 15) * 8;

    float acc[8][8];
    #pragma unroll
    for (int i = 0; i < 8; i++)
        #pragma unroll
        for (int j = 0; j < 8; j++) acc[i][j] = 0.f;

    // Prefetch first K-tile into registers, then smem buffer 0
    float4 pa0 = *(const float4*)(Ap);
    float4 pa1 = *(const float4*)(Ap + (size_t)64 * K);
    float4 pb0 = *(const float4*)(Bp);
    float4 pb1 = *(const float4*)(Bp + (size_t)64 * K);

    As[0][lc+0][lr] = pa0.x; As[0][lc+1][lr] = pa0.y;
    As[0][lc+2][lr] = pa0.z; As[0][lc+3][lr] = pa0.w;
    As[0][lc+0][lr+64] = pa1.x; As[0][lc+1][lr+64] = pa1.y;
    As[0][lc+2][lr+64] = pa1.z; As[0][lc+3][lr+64] = pa1.w;
    Bs[0][lc+0][lr] = pb0.x; Bs[0][lc+1][lr] = pb0.y;
    Bs[0][lc+2][lr] = pb0.z; Bs[0][lc+3][lr] = pb0.w;
    Bs[0][lc+0][lr+64] = pb1.x; Bs[0][lc+1][lr+64] = pb1.y;
    Bs[0][lc+2][lr+64] = pb1.z; Bs[0][lc+3][lr+64] = pb1.w;
    __syncthreads();

    const int NT = K / 16;   // 32 K-tiles
    int buf = 0;
    for (int kt = 0; kt < NT; kt++) {
        // Prefetch next tile global -> regs (overlaps with compute below)
        if (kt + 1 < NT) {
            int k0 = (kt + 1) * 16;
            pa0 = *(const float4*)(Ap + k0);
            pa1 = *(const float4*)(Ap + (size_t)64 * K + k0);
            pb0 = *(const float4*)(Bp + k0);
            pb1 = *(const float4*)(Bp + (size_t)64 * K + k0);
        }

        // Compute on current buffer
        #pragma unroll
        for (int k = 0; k < 16; k++) {
            float ar[8], br[8];
            float4 t0 = *(const float4*)&As[buf][k][tm];
            float4 t1 = *(const float4*)&As[buf][k][tm + 4];
            ar[0]=t0.x; ar[1]=t0.y; ar[2]=t0.z; ar[3]=t0.w;
            ar[4]=t1.x; ar[5]=t1.y; ar[6]=t1.z; ar[7]=t1.w;
            float4 u0 = *(const float4*)&Bs[buf][k][tn];
            float4 u1 = *(const float4*)&Bs[buf][k][tn + 4];
            br[0]=u0.x; br[1]=u0.y; br[2]=u0.z; br[3]=u0.w;
            br[4]=u1.x; br[5]=u1.y; br[6]=u1.z; br[7]=u1.w;
            #pragma unroll
            for (int i = 0; i < 8; i++)
                #pragma unroll
                for (int j = 0; j < 8; j++)
                    acc[i][j] = fmaf(ar[i], br[j], acc[i][j]);
        }

        // Store prefetched regs -> other buffer
        if (kt + 1 < NT) {
            int nb = buf ^ 1;
            As[nb][lc+0][lr] = pa0.x; As[nb][lc+1][lr] = pa0.y;
            As[nb][lc+2][lr] = pa0.z; As[nb][lc+3][lr] = pa0.w;
            As[nb][lc+0][lr+64] = pa1.x; As[nb][lc+1][lr+64] = pa1.y;
            As[nb][lc+2][lr+64] = pa1.z; As[nb][lc+3][lr+64] = pa1.w;
            Bs[nb][lc+0][lr] = pb0.x; Bs[nb][lc+1][lr] = pb0.y;
            Bs[nb][lc+2][lr] = pb0.z; Bs[nb][lc+3][lr] = pb0.w;
            Bs[nb][lc+0][lr+64] = pb1.x; Bs[nb][lc+1][lr+64] = pb1.y;
            Bs[nb][lc+2][lr+64] = pb1.z; Bs[nb][lc+3][lr+64] = pb1.w;
        }
        __syncthreads();
        buf ^= 1;
    }

    float bb[8];
    #pragma unroll
    for (int j = 0; j < 8; j++) bb[j] = bias[bn + tn + j];

    if (mode == 0) {
        #pragma unroll
        for (int i = 0; i < 8; i++) {
            int m = bm + tm + i;
            float* crow = Cc + (size_t)m * N + bn + tn;
            #pragma unroll
            for (int j = 0; j < 8; j++) crow[j] = acc[i][j] + bb[j];
        }
    } else {
        const float inv_bn = rsqrtf(1.f + 1e-5f);
        float gg[8], be[8];
        #pragma unroll
        for (int j = 0; j < 8; j++) { gg[j] = bn_g[bn + tn + j]; be[j] = bn_b[bn + tn + j]; }
        #pragma unroll
        for (int i = 0; i < 8; i++) {
            int m = bm + tm + i;
            int b = m / NTOK, tok = m - b * NTOK;
            #pragma unroll
            for (int j = 0; j < 8; j++) {
                float v = acc[i][j] + bb[j];
                v = fmaxf(v, 0.f) * inv_bn;
                v = v * gg[j] + be[j];
                Cc[((size_t)b * N + (bn + tn + j)) * NTOK + tok] = v;
            }
        }
    }
}

// ---------------------------------------------------------------------------
// Flash attention, fp32 CUDA cores. hd=64, heads=8, nk=1568.
// Block: 256 threads (8 warps), 4 queries per warp => 32 queries / block.
// Main loop: 64-key tiles (lane owns keys lane & lane+32), single fused
// online-softmax update per 64 keys. Tail: one 32-key tile (1568 = 24*64+32).
// Grid: (1568/32 = 49, B*NH = 32)
// ---------------------------------------------------------------------------
#define QPW 4
#define QT  32
__global__ __launch_bounds__(256) void attn_kernel(
    const float* __restrict__ Q, const float* __restrict__ K,
    const float* __restrict__ V, float* __restrict__ T)
{
    int bh = blockIdx.y;
    int b = bh >> 3, h = bh & 7;
    int wid = threadIdx.x >> 5, lane = threadIdx.x & 31;
    int qblk = blockIdx.x * QT;
    int qw = wid * QPW;

    __shared__ float Qs[QT][64];
    __shared__ float Ks[64][65];
    __shared__ float Vs[64][64];

    const float* Qb = Q + ((size_t)b * NTOK + qblk) * C_ + h * HD;
    const float* Kb = K + (size_t)b * NTOK * C_ + h * HD;
    const float* Vb = V + (size_t)b * NTOK * C_ + h * HD;

    // Load Q tile: 32 rows x 64 = 512 float4, 2 per thread
    #pragma unroll
    for (int it = 0; it < 2; it++) {
        int idx = threadIdx.x + it * 256;
        int row = idx >> 4, c4 = (idx & 15) * 4;
        float4 v4 = *(const float4*)(Qb + (size_t)row * C_ + c4);
        *(float4*)&Qs[row][c4] = v4;
    }

    float m[QPW], l[QPW], o0[QPW], o1[QPW];
    #pragma unroll
    for (int q = 0; q < QPW; q++) { m[q] = -1e30f; l[q] = 0.f; o0[q] = 0.f; o1[q] = 0.f; }

    // ---- Main loop: 24 tiles of 64 keys ----
    for (int kt = 0; kt < 24; kt++) {
        __syncthreads();
        // Load 64 rows of K and V: 1024 float4 each, 4 per thread
        #pragma unroll
        for (int it = 0; it < 4; it++) {
            int idx = threadIdx.x + it * 256;
            int row = idx >> 4, c4 = (idx & 15) * 4;
            const float* kr = Kb + (size_t)(kt * 64 + row) * C_ + c4;
            float4 kv = *(const float4*)kr;
            Ks[row][c4 + 0] = kv.x; Ks[row][c4 + 1] = kv.y;
            Ks[row][c4 + 2] = kv.z; Ks[row][c4 + 3] = kv.w;
            float4 vv = *(const float4*)(Vb + (size_t)(kt * 64 + row) * C_ + c4);
            *(float4*)&Vs[row][c4] = vv;
        }
        __syncthreads();

        // Scores: lane owns keys 'lane' and 'lane+32'
        float s0[QPW] = {0.f, 0.f, 0.f, 0.f};
        float s1[QPW] = {0.f, 0.f, 0.f, 0.f};
        #pragma unroll
        for (int d = 0; d < 64; d++) {
            float k0 = Ks[lane][d];
            float k1 = Ks[lane + 32][d];
            #pragma unroll
            for (int q = 0; q < QPW; q++) {
                float qv = Qs[qw + q][d];
                s0[q] = fmaf(qv, k0, s0[q]);
                s1[q] = fmaf(qv, k1, s1[q]);
            }
        }

        // One fused online-softmax update per 64 keys
        #pragma unroll
        for (int q = 0; q < QPW; q++) {
            float sv0 = s0[q] * 0.125f;
            float sv1 = s1[q] * 0.125f;
            float mt = fmaxf(sv0, sv1);
            #pragma unroll
            for (int off = 16; off; off >>= 1)
                mt = fmaxf(mt, __shfl_xor_sync(0xffffffffu, mt, off));
            float mnew = fmaxf(m[q], mt);
            float corr = __expf(m[q] - mnew);
            float p0 = __expf(sv0 - mnew);
            float p1 = __expf(sv1 - mnew);
            float ps = p0 + p1;
            #pragma unroll
            for (int off = 16; off; off >>= 1)
                ps += __shfl_xor_sync(0xffffffffu, ps, off);
            l[q] = l[q] * corr + ps;
            o0[q] *= corr; o1[q] *= corr;
            m[q] = mnew;
            s0[q] = p0; s1[q] = p1;
        }

        // Accumulate P @ V over 64 keys
        #pragma unroll
        for (int j = 0; j < 32; j++) {
            float v0 = Vs[j][lane];
            float v1 = Vs[j][lane + 32];
            #pragma unroll
            for (int q = 0; q < QPW; q++) {
                float pj = __shfl_sync(0xffffffffu, s0[q], j);
                o0[q] = fmaf(pj, v0, o0[q]);
                o1[q] = fmaf(pj, v1, o1[q]);
            }
        }
        #pragma unroll
        for (int j = 0; j < 32; j++) {
            float v0 = Vs[j + 32][lane];
            float v1 = Vs[j + 32][lane + 32];
            #pragma unroll
            for (int q = 0; q < QPW; q++) {
                float pj = __shfl_sync(0xffffffffu, s1[q], j);
                o0[q] = fmaf(pj, v0, o0[q]);
                o1[q] = fmaf(pj, v1, o1[q]);
            }
        }
    }

    // ---- Tail: final 32 keys (1536..1567) ----
    {
        __syncthreads();
        #pragma unroll
        for (int it = 0; it < 2; it++) {
            int idx = threadIdx.x + it * 256;
            int row = idx >> 4, c4 = (idx & 15) * 4;
            const float* kr = Kb + (size_t)(1536 + row) * C_ + c4;
            float4 kv = *(const float4*)kr;
            Ks[row][c4 + 0] = kv.x; Ks[row][c4 + 1] = kv.y;
            Ks[row][c4 + 2] = kv.z; Ks[row][c4 + 3] = kv.w;
            float4 vv = *(const float4*)(Vb + (size_t)(1536 + row) * C_ + c4);
            *(float4*)&Vs[row][c4] = vv;
        }
        __syncthreads();

        float s[QPW] = {0.f, 0.f, 0.f, 0.f};
        #pragma unroll
        for (int d = 0; d < 64; d++) {
            float kd = Ks[lane][d];
            #pragma unroll
            for (int q = 0; q < QPW; q++) s[q] = fmaf(Qs[qw + q][d], kd, s[q]);
        }
        #pragma unroll
        for (int q = 0; q < QPW; q++) {
            float sv = s[q] * 0.125f;
            float mt = sv;
            #pragma unroll
            for (int off = 16; off; off >>= 1)
                mt = fmaxf(mt, __shfl_xor_sync(0xffffffffu, mt, off));
            float mnew = fmaxf(m[q], mt);
            float corr = __expf(m[q] - mnew);
            float p = __expf(sv - mnew);
            float ps = p;
            #pragma unroll
            for (int off = 16; off; off >>= 1)
                ps += __shfl_xor_sync(0xffffffffu, ps, off);
            l[q] = l[q] * corr + ps;
            o0[q] *= corr; o1[q] *= corr;
            m[q] = mnew;
            s[q] = p;
        }
        #pragma unroll
        for (int j = 0; j < 32; j++) {
            float v0 = Vs[j][lane];
            float v1 = Vs[j][lane + 32];
            #pragma unroll
            for (int q = 0; q < QPW; q++) {
                float pj = __shfl_sync(0xffffffffu, s[q], j);
                o0[q] = fmaf(pj, v0, o0[q]);
                o1[q] = fmaf(pj, v1, o1[q]);
            }
        }
    }

    #pragma unroll
    for (int q = 0; q < QPW; q++) {
        float inv = 1.f / l[q];
        float* Tr = T + ((size_t)b * NTOK + qblk + qw + q) * C_ + h * HD;
        Tr[lane]      += o0[q] * inv;
        Tr[lane + 32] += o1[q] * inv;
    }
}

// ---------------------------------------------------------------------------
// Host launcher
// ---------------------------------------------------------------------------
extern "C" void kernel_launch(void* const* d_in, const int* in_sizes, int n_in,
                              void* d_out, int out_size) {
    const float* x1    = (const float*)d_in[0];
    const float* x2    = (const float*)d_in[1];
    const float* Wq1   = (const float*)d_in[2];
    const float* bq1   = (const float*)d_in[3];
    const float* Wk1   = (const float*)d_in[4];
    const float* bk1   = (const float*)d_in[5];
    const float* Wv1   = (const float*)d_in[6];
    const float* bv1   = (const float*)d_in[7];
    const float* ln1_g = (const float*)d_in[8];
    const float* ln1_b = (const float*)d_in[9];
    const float* Wq2   = (const float*)d_in[10];
    const float* bq2   = (const float*)d_in[11];
    const float* Wk2   = (const float*)d_in[12];
    const float* bk2   = (const float*)d_in[13];
    const float* Wv2   = (const float*)d_in[14];
    const float* bv2   = (const float*)d_in[15];
    const float* ln2_g = (const float*)d_in[16];
    const float* ln2_b = (const float*)d_in[17];
    const float* o1w   = (const float*)d_in[18];
    const float* o1b   = (const float*)d_in[19];
    const float* bn1g  = (const float*)d_in[20];
    const float* bn1b  = (const float*)d_in[21];
    const float* o2w   = (const float*)d_in[22];
    const float* o2b   = (const float*)d_in[23];
    const float* bn2g  = (const float*)d_in[24];
    const float* bn2b  = (const float*)d_in[25];
    float* out = (float*)d_out;

    float* S = nullptr;
    cudaGetSymbolAddress((void**)&S, g_scratch);
    const size_t SZ = (size_t)M_ALL * C_;
    float* t1  = S + 0 * SZ;
    float* t2  = S + 1 * SZ;
    float* ln1 = S + 2 * SZ;
    float* ln2 = S + 3 * SZ;
    float* q1  = S + 4 * SZ;
    float* k1  = S + 5 * SZ;
    float* v1  = S + 6 * SZ;
    float* q2  = S + 7 * SZ;
    float* k2  = S + 8 * SZ;
    float* v2  = S + 9 * SZ;

    dim3 tokg(NTOK / 32, C_ / 32, B_), tokb(32, 8);
    tok_kernel<<<tokg, tokb>>>(x1, t1);
    tok_kernel<<<tokg, tokb>>>(x2, t2);

    dim3 gg(C_ / 128, M_ALL / 128);      // (4, 49)
    dim3 ag(NTOK / QT, B_ * NH);         // (49, 32)

    for (int i = 0; i < 3; i++) {
        size_t wo = (size_t)i * C_ * C_;
        size_t bo = (size_t)i * C_;
        ln_kernel<<<M_ALL, 128>>>(t1, ln1_g + bo, ln1_b + bo, ln1);
        ln_kernel<<<M_ALL, 128>>>(t2, ln2_g + bo, ln2_b + bo, ln2);
        gemm_kernel<<<gg, 256>>>(ln1, Wq1 + wo, bq1 + bo, q1, 0, nullptr, nullptr);
        gemm_kernel<<<gg, 256>>>(t2,  Wk1 + wo, bk1 + bo, k1, 0, nullptr, nullptr);
        gemm_kernel<<<gg, 256>>>(t2,  Wv1 + wo, bv1 + bo, v1, 0, nullptr, nullptr);
        gemm_kernel<<<gg, 256>>>(ln2, Wq2 + wo, bq2 + bo, q2, 0, nullptr, nullptr);
        gemm_kernel<<<gg, 256>>>(t1,  Wk2 + wo, bk2 + bo, k2, 0, nullptr, nullptr);
        gemm_kernel<<<gg, 256>>>(t1,  Wv2 + wo, bv2 + bo, v2, 0, nullptr, nullptr);
        attn_kernel<<<ag, 256>>>(q1, k1, v1, t1);
        attn_kernel<<<ag, 256>>>(q2, k2, v2, t2);
    }

    gemm_kernel<<<gg, 256>>>(t1, o1w, o1b, out,                          1, bn1g, bn1b);
    gemm_kernel<<<gg, 256>>>(t2, o2w, o2b, out + (size_t)B_ * C_ * NTOK, 1, bn2g, bn2b);

    (void)in_sizes; (void)n_in; (void)out_size;
}

// round 4
// speedup vs baseline: 1.2367x; 1.2367x over previous
#include <cuda_runtime.h>
#include <math.h>
#include <stdint.h>

// Problem constants
#define B_    4
#define NTOK  1568
#define C_    512
#define NH    8
#define HD    64
#define M_ALL (B_*NTOK)   // 6272

// One big scratch buffer: 10 planes of [6272, 512] floats = 128.45 MB
__device__ float g_scratch[10ull * M_ALL * C_];

__device__ __forceinline__ uint32_t f2tf32(float f) {
    uint32_t u;
    asm("cvt.rna.tf32.f32 %0, %1;" : "=r"(u) : "f"(f));
    return u;
}

// ---------------------------------------------------------------------------
// Tokenize: x [B, C, N] -> t [B, N, C]  (N = T*H*W = 1568)
// ---------------------------------------------------------------------------
__global__ void tok_kernel(const float* __restrict__ x, float* __restrict__ t) {
    __shared__ float tile[32][33];
    int b = blockIdx.z;
    int n0 = blockIdx.x * 32;
    int c0 = blockIdx.y * 32;
    const float* xb = x + (size_t)b * C_ * NTOK;
    float* tb = t + (size_t)b * NTOK * C_;
    int tx = threadIdx.x, ty = threadIdx.y;   // 32 x 8
    #pragma unroll
    for (int i = ty; i < 32; i += 8) {
        int c = c0 + i, n = n0 + tx;
        tile[i][tx] = xb[(size_t)c * NTOK + n];
    }
    __syncthreads();
    #pragma unroll
    for (int i = ty; i < 32; i += 8) {
        int n = n0 + i, c = c0 + tx;
        tb[(size_t)n * C_ + c] = tile[tx][i];
    }
}

// ---------------------------------------------------------------------------
// LayerNorm over last dim (512). One block of 128 threads per token row.
// ---------------------------------------------------------------------------
__global__ void ln_kernel(const float* __restrict__ X, const float* __restrict__ g,
                          const float* __restrict__ bt, float* __restrict__ Y) {
    int row = blockIdx.x;
    const float* x = X + (size_t)row * C_;
    float* y = Y + (size_t)row * C_;
    int tid = threadIdx.x;
    int lane = tid & 31, wid = tid >> 5;

    float4 v = *(const float4*)(x + tid * 4);
    float s  = v.x + v.y + v.z + v.w;
    float s2 = v.x*v.x + v.y*v.y + v.z*v.z + v.w*v.w;

    #pragma unroll
    for (int off = 16; off; off >>= 1) {
        s  += __shfl_xor_sync(0xffffffffu, s,  off);
        s2 += __shfl_xor_sync(0xffffffffu, s2, off);
    }
    __shared__ float smS[4], smS2[4];
    __shared__ float mu_s, rs_s;
    if (lane == 0) { smS[wid] = s; smS2[wid] = s2; }
    __syncthreads();
    if (tid == 0) {
        float S1 = smS[0] + smS[1] + smS[2] + smS[3];
        float S2 = smS2[0] + smS2[1] + smS2[2] + smS2[3];
        float mu = S1 * (1.f / C_);
        float var = S2 * (1.f / C_) - mu * mu;
        mu_s = mu;
        rs_s = rsqrtf(var + 1e-5f);
    }
    __syncthreads();
    float mu = mu_s, rs = rs_s;
    float4 gv = *(const float4*)(g  + tid * 4);
    float4 bv = *(const float4*)(bt + tid * 4);
    float4 o;
    o.x = (v.x - mu) * rs * gv.x + bv.x;
    o.y = (v.y - mu) * rs * gv.y + bv.y;
    o.z = (v.z - mu) * rs * gv.z + bv.z;
    o.w = (v.w - mu) * rs * gv.w + bv.w;
    *(float4*)(y + tid * 4) = o;
}

// ---------------------------------------------------------------------------
// TF32 tensor-core GEMM: C[M,N] = A[M,K] @ B[N,K]^T + bias[N]
// M=6272, N=512, K=512. 128x128 tiles, K-tile 16, double-buffered smem,
// 256 threads = 8 warps, each warp computes 64x32 via m16n8k8 tf32 mma.
// Operands converted to tf32 (round-to-nearest) once at smem-store time.
// Smem row stride 20 words -> fragment loads are bank-conflict-free.
// ---------------------------------------------------------------------------
__global__ __launch_bounds__(256) void gemm_tf32_kernel(
    const float* __restrict__ A, const float* __restrict__ Bw,
    const float* __restrict__ bias, float* __restrict__ Cc)
{
    const int N = 512, K = 512;
    __shared__ uint32_t As[2][128][20];
    __shared__ uint32_t Bs[2][128][20];
    int tid = threadIdx.x;
    int bm = blockIdx.y * 128;
    int bn = blockIdx.x * 128;

    int lr = tid >> 2;             // 0..63
    int lc = (tid & 3) << 2;       // 0,4,8,12
    const float* Ap = A  + (size_t)(bm + lr) * K + lc;
    const float* Bp = Bw + (size_t)(bn + lr) * K + lc;

    int wid = tid >> 5, lane = tid & 31;
    int wm = (wid & 1) * 64;       // warp row offset in tile
    int wn = (wid >> 1) * 32;      // warp col offset in tile
    int qr = lane >> 2;            // 0..7
    int qc = lane & 3;             // 0..3

    float d[4][4][4];
    #pragma unroll
    for (int mi = 0; mi < 4; mi++)
        #pragma unroll
        for (int ni = 0; ni < 4; ni++)
            #pragma unroll
            for (int r = 0; r < 4; r++) d[mi][ni][r] = 0.f;

    // Prefetch first K-tile
    float4 pa0 = *(const float4*)(Ap);
    float4 pa1 = *(const float4*)(Ap + (size_t)64 * K);
    float4 pb0 = *(const float4*)(Bp);
    float4 pb1 = *(const float4*)(Bp + (size_t)64 * K);

    As[0][lr   ][lc+0]=f2tf32(pa0.x); As[0][lr   ][lc+1]=f2tf32(pa0.y);
    As[0][lr   ][lc+2]=f2tf32(pa0.z); As[0][lr   ][lc+3]=f2tf32(pa0.w);
    As[0][lr+64][lc+0]=f2tf32(pa1.x); As[0][lr+64][lc+1]=f2tf32(pa1.y);
    As[0][lr+64][lc+2]=f2tf32(pa1.z); As[0][lr+64][lc+3]=f2tf32(pa1.w);
    Bs[0][lr   ][lc+0]=f2tf32(pb0.x); Bs[0][lr   ][lc+1]=f2tf32(pb0.y);
    Bs[0][lr   ][lc+2]=f2tf32(pb0.z); Bs[0][lr   ][lc+3]=f2tf32(pb0.w);
    Bs[0][lr+64][lc+0]=f2tf32(pb1.x); Bs[0][lr+64][lc+1]=f2tf32(pb1.y);
    Bs[0][lr+64][lc+2]=f2tf32(pb1.z); Bs[0][lr+64][lc+3]=f2tf32(pb1.w);
    __syncthreads();

    const int NT = K / 16;   // 32 K-tiles
    int buf = 0;
    for (int kt = 0; kt < NT; kt++) {
        if (kt + 1 < NT) {
            int k0 = (kt + 1) * 16;
            pa0 = *(const float4*)(Ap + k0);
            pa1 = *(const float4*)(Ap + (size_t)64 * K + k0);
            pb0 = *(const float4*)(Bp + k0);
            pb1 = *(const float4*)(Bp + (size_t)64 * K + k0);
        }

        #pragma unroll
        for (int ks = 0; ks < 2; ks++) {
            int k0 = ks * 8;
            uint32_t a[4][4], bfr[4][2];
            #pragma unroll
            for (int mi = 0; mi < 4; mi++) {
                int r0 = wm + mi * 16 + qr;
                a[mi][0] = As[buf][r0    ][k0 + qc];
                a[mi][1] = As[buf][r0 + 8][k0 + qc];
                a[mi][2] = As[buf][r0    ][k0 + qc + 4];
                a[mi][3] = As[buf][r0 + 8][k0 + qc + 4];
            }
            #pragma unroll
            for (int ni = 0; ni < 4; ni++) {
                int c0 = wn + ni * 8 + qr;
                bfr[ni][0] = Bs[buf][c0][k0 + qc];
                bfr[ni][1] = Bs[buf][c0][k0 + qc + 4];
            }
            #pragma unroll
            for (int mi = 0; mi < 4; mi++)
                #pragma unroll
                for (int ni = 0; ni < 4; ni++) {
                    asm volatile(
                        "mma.sync.aligned.m16n8k8.row.col.f32.tf32.tf32.f32 "
                        "{%0,%1,%2,%3}, {%4,%5,%6,%7}, {%8,%9}, {%0,%1,%2,%3};\n"
                        : "+f"(d[mi][ni][0]), "+f"(d[mi][ni][1]),
                          "+f"(d[mi][ni][2]), "+f"(d[mi][ni][3])
                        : "r"(a[mi][0]), "r"(a[mi][1]), "r"(a[mi][2]), "r"(a[mi][3]),
                          "r"(bfr[ni][0]), "r"(bfr[ni][1]));
                }
        }

        if (kt + 1 < NT) {
            int nb = buf ^ 1;
            As[nb][lr   ][lc+0]=f2tf32(pa0.x); As[nb][lr   ][lc+1]=f2tf32(pa0.y);
            As[nb][lr   ][lc+2]=f2tf32(pa0.z); As[nb][lr   ][lc+3]=f2tf32(pa0.w);
            As[nb][lr+64][lc+0]=f2tf32(pa1.x); As[nb][lr+64][lc+1]=f2tf32(pa1.y);
            As[nb][lr+64][lc+2]=f2tf32(pa1.z); As[nb][lr+64][lc+3]=f2tf32(pa1.w);
            Bs[nb][lr   ][lc+0]=f2tf32(pb0.x); Bs[nb][lr   ][lc+1]=f2tf32(pb0.y);
            Bs[nb][lr   ][lc+2]=f2tf32(pb0.z); Bs[nb][lr   ][lc+3]=f2tf32(pb0.w);
            Bs[nb][lr+64][lc+0]=f2tf32(pb1.x); Bs[nb][lr+64][lc+1]=f2tf32(pb1.y);
            Bs[nb][lr+64][lc+2]=f2tf32(pb1.z); Bs[nb][lr+64][lc+3]=f2tf32(pb1.w);
        }
        __syncthreads();
        buf ^= 1;
    }

    // Epilogue: bias add, float2 stores
    #pragma unroll
    for (int mi = 0; mi < 4; mi++) {
        int row0 = bm + wm + mi * 16 + qr;
        #pragma unroll
        for (int ni = 0; ni < 4; ni++) {
            int col0 = bn + wn + ni * 8 + qc * 2;
            float b0 = bias[col0], b1 = bias[col0 + 1];
            float2 v0 = make_float2(d[mi][ni][0] + b0, d[mi][ni][1] + b1);
            float2 v1 = make_float2(d[mi][ni][2] + b0, d[mi][ni][3] + b1);
            *(float2*)(Cc + (size_t)row0 * N + col0)       = v0;
            *(float2*)(Cc + (size_t)(row0 + 8) * N + col0) = v1;
        }
    }
}

// ---------------------------------------------------------------------------
// FP32 SGEMM (kept for the precision-critical output head only).
// mode 1: out-head: relu(v)*rsqrt(1+eps)*bn_g[n]+bn_b[n],
//         stored transposed per batch: out[(b*N + n)*1568 + tok]
// ---------------------------------------------------------------------------
__global__ __launch_bounds__(256) void gemm_kernel(
    const float* __restrict__ A, const float* __restrict__ Bw,
    const float* __restrict__ bias, float* __restrict__ Cc,
    int mode, const float* __restrict__ bn_g, const float* __restrict__ bn_b)
{
    const int N = 512, K = 512;
    __shared__ float As[2][16][132];
    __shared__ float Bs[2][16][132];
    int tid = threadIdx.x;
    int bm = blockIdx.y * 128;
    int bn = blockIdx.x * 128;

    int lr = tid >> 2;
    int lc = (tid & 3) << 2;
    const float* Ap = A  + (size_t)(bm + lr) * K + lc;
    const float* Bp = Bw + (size_t)(bn + lr) * K + lc;

    int tm = (tid >> 4) * 8;
    int tn = (tid & 15) * 8;

    float acc[8][8];
    #pragma unroll
    for (int i = 0; i < 8; i++)
        #pragma unroll
        for (int j = 0; j < 8; j++) acc[i][j] = 0.f;

    float4 pa0 = *(const float4*)(Ap);
    float4 pa1 = *(const float4*)(Ap + (size_t)64 * K);
    float4 pb0 = *(const float4*)(Bp);
    float4 pb1 = *(const float4*)(Bp + (size_t)64 * K);

    As[0][lc+0][lr] = pa0.x; As[0][lc+1][lr] = pa0.y;
    As[0][lc+2][lr] = pa0.z; As[0][lc+3][lr] = pa0.w;
    As[0][lc+0][lr+64] = pa1.x; As[0][lc+1][lr+64] = pa1.y;
    As[0][lc+2][lr+64] = pa1.z; As[0][lc+3][lr+64] = pa1.w;
    Bs[0][lc+0][lr] = pb0.x; Bs[0][lc+1][lr] = pb0.y;
    Bs[0][lc+2][lr] = pb0.z; Bs[0][lc+3][lr] = pb0.w;
    Bs[0][lc+0][lr+64] = pb1.x; Bs[0][lc+1][lr+64] = pb1.y;
    Bs[0][lc+2][lr+64] = pb1.z; Bs[0][lc+3][lr+64] = pb1.w;
    __syncthreads();

    const int NT = K / 16;
    int buf = 0;
    for (int kt = 0; kt < NT; kt++) {
        if (kt + 1 < NT) {
            int k0 = (kt + 1) * 16;
            pa0 = *(const float4*)(Ap + k0);
            pa1 = *(const float4*)(Ap + (size_t)64 * K + k0);
            pb0 = *(const float4*)(Bp + k0);
            pb1 = *(const float4*)(Bp + (size_t)64 * K + k0);
        }

        #pragma unroll
        for (int k = 0; k < 16; k++) {
            float ar[8], br[8];
            float4 t0 = *(const float4*)&As[buf][k][tm];
            float4 t1 = *(const float4*)&As[buf][k][tm + 4];
            ar[0]=t0.x; ar[1]=t0.y; ar[2]=t0.z; ar[3]=t0.w;
            ar[4]=t1.x; ar[5]=t1.y; ar[6]=t1.z; ar[7]=t1.w;
            float4 u0 = *(const float4*)&Bs[buf][k][tn];
            float4 u1 = *(const float4*)&Bs[buf][k][tn + 4];
            br[0]=u0.x; br[1]=u0.y; br[2]=u0.z; br[3]=u0.w;
            br[4]=u1.x; br[5]=u1.y; br[6]=u1.z; br[7]=u1.w;
            #pragma unroll
            for (int i = 0; i < 8; i++)
                #pragma unroll
                for (int j = 0; j < 8; j++)
                    acc[i][j] = fmaf(ar[i], br[j], acc[i][j]);
        }

        if (kt + 1 < NT) {
            int nb = buf ^ 1;
            As[nb][lc+0][lr] = pa0.x; As[nb][lc+1][lr] = pa0.y;
            As[nb][lc+2][lr] = pa0.z; As[nb][lc+3][lr] = pa0.w;
            As[nb][lc+0][lr+64] = pa1.x; As[nb][lc+1][lr+64] = pa1.y;
            As[nb][lc+2][lr+64] = pa1.z; As[nb][lc+3][lr+64] = pa1.w;
            Bs[nb][lc+0][lr] = pb0.x; Bs[nb][lc+1][lr] = pb0.y;
            Bs[nb][lc+2][lr] = pb0.z; Bs[nb][lc+3][lr] = pb0.w;
            Bs[nb][lc+0][lr+64] = pb1.x; Bs[nb][lc+1][lr+64] = pb1.y;
            Bs[nb][lc+2][lr+64] = pb1.z; Bs[nb][lc+3][lr+64] = pb1.w;
        }
        __syncthreads();
        buf ^= 1;
    }

    float bb[8];
    #pragma unroll
    for (int j = 0; j < 8; j++) bb[j] = bias[bn + tn + j];

    if (mode == 0) {
        #pragma unroll
        for (int i = 0; i < 8; i++) {
            int m = bm + tm + i;
            float* crow = Cc + (size_t)m * N + bn + tn;
            #pragma unroll
            for (int j = 0; j < 8; j++) crow[j] = acc[i][j] + bb[j];
        }
    } else {
        const float inv_bn = rsqrtf(1.f + 1e-5f);
        float gg[8], be[8];
        #pragma unroll
        for (int j = 0; j < 8; j++) { gg[j] = bn_g[bn + tn + j]; be[j] = bn_b[bn + tn + j]; }
        #pragma unroll
        for (int i = 0; i < 8; i++) {
            int m = bm + tm + i;
            int b = m / NTOK, tok = m - b * NTOK;
            #pragma unroll
            for (int j = 0; j < 8; j++) {
                float v = acc[i][j] + bb[j];
                v = fmaxf(v, 0.f) * inv_bn;
                v = v * gg[j] + be[j];
                Cc[((size_t)b * N + (bn + tn + j)) * NTOK + tok] = v;
            }
        }
    }
}

// ---------------------------------------------------------------------------
// Flash attention, fp32 CUDA cores. hd=64, heads=8, nk=1568.
// Block: 256 threads (8 warps), 4 queries per warp => 32 queries / block.
// Main loop: 64-key tiles (lane owns keys lane & lane+32), single fused
// online-softmax update per 64 keys. Tail: one 32-key tile (1568 = 24*64+32).
// Grid: (1568/32 = 49, B*NH = 32)
// ---------------------------------------------------------------------------
#define QPW 4
#define QT  32
__global__ __launch_bounds__(256) void attn_kernel(
    const float* __restrict__ Q, const float* __restrict__ K,
    const float* __restrict__ V, float* __restrict__ T)
{
    int bh = blockIdx.y;
    int b = bh >> 3, h = bh & 7;
    int wid = threadIdx.x >> 5, lane = threadIdx.x & 31;
    int qblk = blockIdx.x * QT;
    int qw = wid * QPW;

    __shared__ float Qs[QT][64];
    __shared__ float Ks[64][65];
    __shared__ float Vs[64][64];

    const float* Qb = Q + ((size_t)b * NTOK + qblk) * C_ + h * HD;
    const float* Kb = K + (size_t)b * NTOK * C_ + h * HD;
    const float* Vb = V + (size_t)b * NTOK * C_ + h * HD;

    #pragma unroll
    for (int it = 0; it < 2; it++) {
        int idx = threadIdx.x + it * 256;
        int row = idx >> 4, c4 = (idx & 15) * 4;
        float4 v4 = *(const float4*)(Qb + (size_t)row * C_ + c4);
        *(float4*)&Qs[row][c4] = v4;
    }

    float m[QPW], l[QPW], o0[QPW], o1[QPW];
    #pragma unroll
    for (int q = 0; q < QPW; q++) { m[q] = -1e30f; l[q] = 0.f; o0[q] = 0.f; o1[q] = 0.f; }

    for (int kt = 0; kt < 24; kt++) {
        __syncthreads();
        #pragma unroll
        for (int it = 0; it < 4; it++) {
            int idx = threadIdx.x + it * 256;
            int row = idx >> 4, c4 = (idx & 15) * 4;
            const float* kr = Kb + (size_t)(kt * 64 + row) * C_ + c4;
            float4 kv = *(const float4*)kr;
            Ks[row][c4 + 0] = kv.x; Ks[row][c4 + 1] = kv.y;
            Ks[row][c4 + 2] = kv.z; Ks[row][c4 + 3] = kv.w;
            float4 vv = *(const float4*)(Vb + (size_t)(kt * 64 + row) * C_ + c4);
            *(float4*)&Vs[row][c4] = vv;
        }
        __syncthreads();

        float s0[QPW] = {0.f, 0.f, 0.f, 0.f};
        float s1[QPW] = {0.f, 0.f, 0.f, 0.f};
        #pragma unroll
        for (int d = 0; d < 64; d++) {
            float k0 = Ks[lane][d];
            float k1 = Ks[lane + 32][d];
            #pragma unroll
            for (int q = 0; q < QPW; q++) {
                float qv = Qs[qw + q][d];
                s0[q] = fmaf(qv, k0, s0[q]);
                s1[q] = fmaf(qv, k1, s1[q]);
            }
        }

        #pragma unroll
        for (int q = 0; q < QPW; q++) {
            float sv0 = s0[q] * 0.125f;
            float sv1 = s1[q] * 0.125f;
            float mt = fmaxf(sv0, sv1);
            #pragma unroll
            for (int off = 16; off; off >>= 1)
                mt = fmaxf(mt, __shfl_xor_sync(0xffffffffu, mt, off));
            float mnew = fmaxf(m[q], mt);
            float corr = __expf(m[q] - mnew);
            float p0 = __expf(sv0 - mnew);
            float p1 = __expf(sv1 - mnew);
            float ps = p0 + p1;
            #pragma unroll
            for (int off = 16; off; off >>= 1)
                ps += __shfl_xor_sync(0xffffffffu, ps, off);
            l[q] = l[q] * corr + ps;
            o0[q] *= corr; o1[q] *= corr;
            m[q] = mnew;
            s0[q] = p0; s1[q] = p1;
        }

        #pragma unroll
        for (int j = 0; j < 32; j++) {
            float v0 = Vs[j][lane];
            float v1 = Vs[j][lane + 32];
            #pragma unroll
            for (int q = 0; q < QPW; q++) {
                float pj = __shfl_sync(0xffffffffu, s0[q], j);
                o0[q] = fmaf(pj, v0, o0[q]);
                o1[q] = fmaf(pj, v1, o1[q]);
            }
        }
        #pragma unroll
        for (int j = 0; j < 32; j++) {
            float v0 = Vs[j + 32][lane];
            float v1 = Vs[j + 32][lane + 32];
            #pragma unroll
            for (int q = 0; q < QPW; q++) {
                float pj = __shfl_sync(0xffffffffu, s1[q], j);
                o0[q] = fmaf(pj, v0, o0[q]);
                o1[q] = fmaf(pj, v1, o1[q]);
            }
        }
    }

    // Tail: final 32 keys
    {
        __syncthreads();
        #pragma unroll
        for (int it = 0; it < 2; it++) {
            int idx = threadIdx.x + it * 256;
            int row = idx >> 4, c4 = (idx & 15) * 4;
            const float* kr = Kb + (size_t)(1536 + row) * C_ + c4;
            float4 kv = *(const float4*)kr;
            Ks[row][c4 + 0] = kv.x; Ks[row][c4 + 1] = kv.y;
            Ks[row][c4 + 2] = kv.z; Ks[row][c4 + 3] = kv.w;
            float4 vv = *(const float4*)(Vb + (size_t)(1536 + row) * C_ + c4);
            *(float4*)&Vs[row][c4] = vv;
        }
        __syncthreads();

        float s[QPW] = {0.f, 0.f, 0.f, 0.f};
        #pragma unroll
        for (int d = 0; d < 64; d++) {
            float kd = Ks[lane][d];
            #pragma unroll
            for (int q = 0; q < QPW; q++) s[q] = fmaf(Qs[qw + q][d], kd, s[q]);
        }
        #pragma unroll
        for (int q = 0; q < QPW; q++) {
            float sv = s[q] * 0.125f;
            float mt = sv;
            #pragma unroll
            for (int off = 16; off; off >>= 1)
                mt = fmaxf(mt, __shfl_xor_sync(0xffffffffu, mt, off));
            float mnew = fmaxf(m[q], mt);
            float corr = __expf(m[q] - mnew);
            float p = __expf(sv - mnew);
            float ps = p;
            #pragma unroll
            for (int off = 16; off; off >>= 1)
                ps += __shfl_xor_sync(0xffffffffu, ps, off);
            l[q] = l[q] * corr + ps;
            o0[q] *= corr; o1[q] *= corr;
            m[q] = mnew;
            s[q] = p;
        }
        #pragma unroll
        for (int j = 0; j < 32; j++) {
            float v0 = Vs[j][lane];
            float v1 = Vs[j][lane + 32];
            #pragma unroll
            for (int q = 0; q < QPW; q++) {
                float pj = __shfl_sync(0xffffffffu, s[q], j);
                o0[q] = fmaf(pj, v0, o0[q]);
                o1[q] = fmaf(pj, v1, o1[q]);
            }
        }
    }

    #pragma unroll
    for (int q = 0; q < QPW; q++) {
        float inv = 1.f / l[q];
        float* Tr = T + ((size_t)b * NTOK + qblk + qw + q) * C_ + h * HD;
        Tr[lane]      += o0[q] * inv;
        Tr[lane + 32] += o1[q] * inv;
    }
}

// ---------------------------------------------------------------------------
// Host launcher
// ---------------------------------------------------------------------------
extern "C" void kernel_launch(void* const* d_in, const int* in_sizes, int n_in,
                              void* d_out, int out_size) {
    const float* x1    = (const float*)d_in[0];
    const float* x2    = (const float*)d_in[1];
    const float* Wq1   = (const float*)d_in[2];
    const float* bq1   = (const float*)d_in[3];
    const float* Wk1   = (const float*)d_in[4];
    const float* bk1   = (const float*)d_in[5];
    const float* Wv1   = (const float*)d_in[6];
    const float* bv1   = (const float*)d_in[7];
    const float* ln1_g = (const float*)d_in[8];
    const float* ln1_b = (const float*)d_in[9];
    const float* Wq2   = (const float*)d_in[10];
    const float* bq2   = (const float*)d_in[11];
    const float* Wk2   = (const float*)d_in[12];
    const float* bk2   = (const float*)d_in[13];
    const float* Wv2   = (const float*)d_in[14];
    const float* bv2   = (const float*)d_in[15];
    const float* ln2_g = (const float*)d_in[16];
    const float* ln2_b = (const float*)d_in[17];
    const float* o1w   = (const float*)d_in[18];
    const float* o1b   = (const float*)d_in[19];
    const float* bn1g  = (const float*)d_in[20];
    const float* bn1b  = (const float*)d_in[21];
    const float* o2w   = (const float*)d_in[22];
    const float* o2b   = (const float*)d_in[23];
    const float* bn2g  = (const float*)d_in[24];
    const float* bn2b  = (const float*)d_in[25];
    float* out = (float*)d_out;

    float* S = nullptr;
    cudaGetSymbolAddress((void**)&S, g_scratch);
    const size_t SZ = (size_t)M_ALL * C_;
    float* t1  = S + 0 * SZ;
    float* t2  = S + 1 * SZ;
    float* ln1 = S + 2 * SZ;
    float* ln2 = S + 3 * SZ;
    float* q1  = S + 4 * SZ;
    float* k1  = S + 5 * SZ;
    float* v1  = S + 6 * SZ;
    float* q2  = S + 7 * SZ;
    float* k2  = S + 8 * SZ;
    float* v2  = S + 9 * SZ;

    dim3 tokg(NTOK / 32, C_ / 32, B_), tokb(32, 8);
    tok_kernel<<<tokg, tokb>>>(x1, t1);
    tok_kernel<<<tokg, tokb>>>(x2, t2);

    dim3 gg(C_ / 128, M_ALL / 128);      // (4, 49)
    dim3 ag(NTOK / QT, B_ * NH);         // (49, 32)

    for (int i = 0; i < 3; i++) {
        size_t wo = (size_t)i * C_ * C_;
        size_t bo = (size_t)i * C_;
        ln_kernel<<<M_ALL, 128>>>(t1, ln1_g + bo, ln1_b + bo, ln1);
        ln_kernel<<<M_ALL, 128>>>(t2, ln2_g + bo, ln2_b + bo, ln2);
        gemm_tf32_kernel<<<gg, 256>>>(ln1, Wq1 + wo, bq1 + bo, q1);
        gemm_tf32_kernel<<<gg, 256>>>(t2,  Wk1 + wo, bk1 + bo, k1);
        gemm_tf32_kernel<<<gg, 256>>>(t2,  Wv1 + wo, bv1 + bo, v1);
        gemm_tf32_kernel<<<gg, 256>>>(ln2, Wq2 + wo, bq2 + bo, q2);
        gemm_tf32_kernel<<<gg, 256>>>(t1,  Wk2 + wo, bk2 + bo, k2);
        gemm_tf32_kernel<<<gg, 256>>>(t1,  Wv2 + wo, bv2 + bo, v2);
        attn_kernel<<<ag, 256>>>(q1, k1, v1, t1);
        attn_kernel<<<ag, 256>>>(q2, k2, v2, t2);
    }

    gemm_kernel<<<gg, 256>>>(t1, o1w, o1b, out,                          1, bn1g, bn1b);
    gemm_kernel<<<gg, 256>>>(t2, o2w, o2b, out + (size_t)B_ * C_ * NTOK, 1, bn2g, bn2b);

    (void)in_sizes; (void)n_in; (void)out_size;
}

// round 7
// speedup vs baseline: 2.5428x; 2.0561x over previous
#include <cuda_runtime.h>
#include <math.h>
#include <stdint.h>

// Problem constants
#define B_    4
#define NTOK  1568
#define C_    512
#define NH    8
#define HD    64
#define M_ALL (B_*NTOK)   // 6272

// One big scratch buffer: 10 planes of [6272, 512] floats = 128.45 MB
__device__ float g_scratch[10ull * M_ALL * C_];

__device__ __forceinline__ uint32_t f2tf32(float f) {
    uint32_t u;
    asm("cvt.rna.tf32.f32 %0, %1;" : "=r"(u) : "f"(f));
    return u;
}

__device__ __forceinline__ void mma_tf32(float d[4], const uint32_t a[4], const uint32_t b[2]) {
    asm volatile(
        "mma.sync.aligned.m16n8k8.row.col.f32.tf32.tf32.f32 "
        "{%0,%1,%2,%3}, {%4,%5,%6,%7}, {%8,%9}, {%0,%1,%2,%3};\n"
        : "+f"(d[0]), "+f"(d[1]), "+f"(d[2]), "+f"(d[3])
        : "r"(a[0]), "r"(a[1]), "r"(a[2]), "r"(a[3]),
          "r"(b[0]), "r"(b[1]));
}

// ---------------------------------------------------------------------------
// Tokenize: x [B, C, N] -> t [B, N, C]  (N = T*H*W = 1568)
// ---------------------------------------------------------------------------
__global__ void tok_kernel(const float* __restrict__ x, float* __restrict__ t) {
    __shared__ float tile[32][33];
    int b = blockIdx.z;
    int n0 = blockIdx.x * 32;
    int c0 = blockIdx.y * 32;
    const float* xb = x + (size_t)b * C_ * NTOK;
    float* tb = t + (size_t)b * NTOK * C_;
    int tx = threadIdx.x, ty = threadIdx.y;   // 32 x 8
    #pragma unroll
    for (int i = ty; i < 32; i += 8) {
        int c = c0 + i, n = n0 + tx;
        tile[i][tx] = xb[(size_t)c * NTOK + n];
    }
    __syncthreads();
    #pragma unroll
    for (int i = ty; i < 32; i += 8) {
        int n = n0 + i, c = c0 + tx;
        tb[(size_t)n * C_ + c] = tile[tx][i];
    }
}

// ---------------------------------------------------------------------------
// LayerNorm over last dim (512). One block of 128 threads per token row.
// ---------------------------------------------------------------------------
__global__ void ln_kernel(const float* __restrict__ X, const float* __restrict__ g,
                          const float* __restrict__ bt, float* __restrict__ Y) {
    int row = blockIdx.x;
    const float* x = X + (size_t)row * C_;
    float* y = Y + (size_t)row * C_;
    int tid = threadIdx.x;
    int lane = tid & 31, wid = tid >> 5;

    float4 v = *(const float4*)(x + tid * 4);
    float s  = v.x + v.y + v.z + v.w;
    float s2 = v.x*v.x + v.y*v.y + v.z*v.z + v.w*v.w;

    #pragma unroll
    for (int off = 16; off; off >>= 1) {
        s  += __shfl_xor_sync(0xffffffffu, s,  off);
        s2 += __shfl_xor_sync(0xffffffffu, s2, off);
    }
    __shared__ float smS[4], smS2[4];
    __shared__ float mu_s, rs_s;
    if (lane == 0) { smS[wid] = s; smS2[wid] = s2; }
    __syncthreads();
    if (tid == 0) {
        float S1 = smS[0] + smS[1] + smS[2] + smS[3];
        float S2 = smS2[0] + smS2[1] + smS2[2] + smS2[3];
        float mu = S1 * (1.f / C_);
        float var = S2 * (1.f / C_) - mu * mu;
        mu_s = mu;
        rs_s = rsqrtf(var + 1e-5f);
    }
    __syncthreads();
    float mu = mu_s, rs = rs_s;
    float4 gv = *(const float4*)(g  + tid * 4);
    float4 bv = *(const float4*)(bt + tid * 4);
    float4 o;
    o.x = (v.x - mu) * rs * gv.x + bv.x;
    o.y = (v.y - mu) * rs * gv.y + bv.y;
    o.z = (v.z - mu) * rs * gv.z + bv.z;
    o.w = (v.w - mu) * rs * gv.w + bv.w;
    *(float4*)(y + tid * 4) = o;
}

// ---------------------------------------------------------------------------
// TF32 tensor-core GEMM: C[M,N] = A[M,K] @ B[N,K]^T + bias[N]
// ---------------------------------------------------------------------------
__global__ __launch_bounds__(256) void gemm_tf32_kernel(
    const float* __restrict__ A, const float* __restrict__ Bw,
    const float* __restrict__ bias, float* __restrict__ Cc)
{
    const int N = 512, K = 512;
    __shared__ uint32_t As[2][128][20];
    __shared__ uint32_t Bs[2][128][20];
    int tid = threadIdx.x;
    int bm = blockIdx.y * 128;
    int bn = blockIdx.x * 128;

    int lr = tid >> 2;             // 0..63
    int lc = (tid & 3) << 2;       // 0,4,8,12
    const float* Ap = A  + (size_t)(bm + lr) * K + lc;
    const float* Bp = Bw + (size_t)(bn + lr) * K + lc;

    int wid = tid >> 5, lane = tid & 31;
    int wm = (wid & 1) * 64;
    int wn = (wid >> 1) * 32;
    int qr = lane >> 2;
    int qc = lane & 3;

    float d[4][4][4];
    #pragma unroll
    for (int mi = 0; mi < 4; mi++)
        #pragma unroll
        for (int ni = 0; ni < 4; ni++)
            #pragma unroll
            for (int r = 0; r < 4; r++) d[mi][ni][r] = 0.f;

    float4 pa0 = *(const float4*)(Ap);
    float4 pa1 = *(const float4*)(Ap + (size_t)64 * K);
    float4 pb0 = *(const float4*)(Bp);
    float4 pb1 = *(const float4*)(Bp + (size_t)64 * K);

    As[0][lr   ][lc+0]=f2tf32(pa0.x); As[0][lr   ][lc+1]=f2tf32(pa0.y);
    As[0][lr   ][lc+2]=f2tf32(pa0.z); As[0][lr   ][lc+3]=f2tf32(pa0.w);
    As[0][lr+64][lc+0]=f2tf32(pa1.x); As[0][lr+64][lc+1]=f2tf32(pa1.y);
    As[0][lr+64][lc+2]=f2tf32(pa1.z); As[0][lr+64][lc+3]=f2tf32(pa1.w);
    Bs[0][lr   ][lc+0]=f2tf32(pb0.x); Bs[0][lr   ][lc+1]=f2tf32(pb0.y);
    Bs[0][lr   ][lc+2]=f2tf32(pb0.z); Bs[0][lr   ][lc+3]=f2tf32(pb0.w);
    Bs[0][lr+64][lc+0]=f2tf32(pb1.x); Bs[0][lr+64][lc+1]=f2tf32(pb1.y);
    Bs[0][lr+64][lc+2]=f2tf32(pb1.z); Bs[0][lr+64][lc+3]=f2tf32(pb1.w);
    __syncthreads();

    const int NT = K / 16;
    int buf = 0;
    for (int kt = 0; kt < NT; kt++) {
        if (kt + 1 < NT) {
            int k0 = (kt + 1) * 16;
            pa0 = *(const float4*)(Ap + k0);
            pa1 = *(const float4*)(Ap + (size_t)64 * K + k0);
            pb0 = *(const float4*)(Bp + k0);
            pb1 = *(const float4*)(Bp + (size_t)64 * K + k0);
        }

        #pragma unroll
        for (int ks = 0; ks < 2; ks++) {
            int k0 = ks * 8;
            uint32_t a[4][4], bfr[4][2];
            #pragma unroll
            for (int mi = 0; mi < 4; mi++) {
                int r0 = wm + mi * 16 + qr;
                a[mi][0] = As[buf][r0    ][k0 + qc];
                a[mi][1] = As[buf][r0 + 8][k0 + qc];
                a[mi][2] = As[buf][r0    ][k0 + qc + 4];
                a[mi][3] = As[buf][r0 + 8][k0 + qc + 4];
            }
            #pragma unroll
            for (int ni = 0; ni < 4; ni++) {
                int c0 = wn + ni * 8 + qr;
                bfr[ni][0] = Bs[buf][c0][k0 + qc];
                bfr[ni][1] = Bs[buf][c0][k0 + qc + 4];
            }
            #pragma unroll
            for (int mi = 0; mi < 4; mi++)
                #pragma unroll
                for (int ni = 0; ni < 4; ni++)
                    mma_tf32(d[mi][ni], a[mi], bfr[ni]);
        }

        if (kt + 1 < NT) {
            int nb = buf ^ 1;
            As[nb][lr   ][lc+0]=f2tf32(pa0.x); As[nb][lr   ][lc+1]=f2tf32(pa0.y);
            As[nb][lr   ][lc+2]=f2tf32(pa0.z); As[nb][lr   ][lc+3]=f2tf32(pa0.w);
            As[nb][lr+64][lc+0]=f2tf32(pa1.x); As[nb][lr+64][lc+1]=f2tf32(pa1.y);
            As[nb][lr+64][lc+2]=f2tf32(pa1.z); As[nb][lr+64][lc+3]=f2tf32(pa1.w);
            Bs[nb][lr   ][lc+0]=f2tf32(pb0.x); Bs[nb][lr   ][lc+1]=f2tf32(pb0.y);
            Bs[nb][lr   ][lc+2]=f2tf32(pb0.z); Bs[nb][lr   ][lc+3]=f2tf32(pb0.w);
            Bs[nb][lr+64][lc+0]=f2tf32(pb1.x); Bs[nb][lr+64][lc+1]=f2tf32(pb1.y);
            Bs[nb][lr+64][lc+2]=f2tf32(pb1.z); Bs[nb][lr+64][lc+3]=f2tf32(pb1.w);
        }
        __syncthreads();
        buf ^= 1;
    }

    #pragma unroll
    for (int mi = 0; mi < 4; mi++) {
        int row0 = bm + wm + mi * 16 + qr;
        #pragma unroll
        for (int ni = 0; ni < 4; ni++) {
            int col0 = bn + wn + ni * 8 + qc * 2;
            float b0 = bias[col0], b1 = bias[col0 + 1];
            float2 v0 = make_float2(d[mi][ni][0] + b0, d[mi][ni][1] + b1);
            float2 v1 = make_float2(d[mi][ni][2] + b0, d[mi][ni][3] + b1);
            *(float2*)(Cc + (size_t)row0 * N + col0)       = v0;
            *(float2*)(Cc + (size_t)(row0 + 8) * N + col0) = v1;
        }
    }
}

// ---------------------------------------------------------------------------
// FP32 SGEMM (precision-critical output head only).
// out-head: relu(v)*rsqrt(1+eps)*bn_g[n]+bn_b[n], transposed store.
// ---------------------------------------------------------------------------
__global__ __launch_bounds__(256) void gemm_kernel(
    const float* __restrict__ A, const float* __restrict__ Bw,
    const float* __restrict__ bias, float* __restrict__ Cc,
    const float* __restrict__ bn_g, const float* __restrict__ bn_b)
{
    const int N = 512, K = 512;
    __shared__ float As[2][16][132];
    __shared__ float Bs[2][16][132];
    int tid = threadIdx.x;
    int bm = blockIdx.y * 128;
    int bn = blockIdx.x * 128;

    int lr = tid >> 2;
    int lc = (tid & 3) << 2;
    const float* Ap = A  + (size_t)(bm + lr) * K + lc;
    const float* Bp = Bw + (size_t)(bn + lr) * K + lc;

    int tm = (tid >> 4) * 8;
    int tn = (tid & 15) * 8;

    float acc[8][8];
    #pragma unroll
    for (int i = 0; i < 8; i++)
        #pragma unroll
        for (int j = 0; j < 8; j++) acc[i][j] = 0.f;

    float4 pa0 = *(const float4*)(Ap);
    float4 pa1 = *(const float4*)(Ap + (size_t)64 * K);
    float4 pb0 = *(const float4*)(Bp);
    float4 pb1 = *(const float4*)(Bp + (size_t)64 * K);

    As[0][lc+0][lr] = pa0.x; As[0][lc+1][lr] = pa0.y;
    As[0][lc+2][lr] = pa0.z; As[0][lc+3][lr] = pa0.w;
    As[0][lc+0][lr+64] = pa1.x; As[0][lc+1][lr+64] = pa1.y;
    As[0][lc+2][lr+64] = pa1.z; As[0][lc+3][lr+64] = pa1.w;
    Bs[0][lc+0][lr] = pb0.x; Bs[0][lc+1][lr] = pb0.y;
    Bs[0][lc+2][lr] = pb0.z; Bs[0][lc+3][lr] = pb0.w;
    Bs[0][lc+0][lr+64] = pb1.x; Bs[0][lc+1][lr+64] = pb1.y;
    Bs[0][lc+2][lr+64] = pb1.z; Bs[0][lc+3][lr+64] = pb1.w;
    __syncthreads();

    const int NT = K / 16;
    int buf = 0;
    for (int kt = 0; kt < NT; kt++) {
        if (kt + 1 < NT) {
            int k0 = (kt + 1) * 16;
            pa0 = *(const float4*)(Ap + k0);
            pa1 = *(const float4*)(Ap + (size_t)64 * K + k0);
            pb0 = *(const float4*)(Bp + k0);
            pb1 = *(const float4*)(Bp + (size_t)64 * K + k0);
        }

        #pragma unroll
        for (int k = 0; k < 16; k++) {
            float ar[8], br[8];
            float4 t0 = *(const float4*)&As[buf][k][tm];
            float4 t1 = *(const float4*)&As[buf][k][tm + 4];
            ar[0]=t0.x; ar[1]=t0.y; ar[2]=t0.z; ar[3]=t0.w;
            ar[4]=t1.x; ar[5]=t1.y; ar[6]=t1.z; ar[7]=t1.w;
            float4 u0 = *(const float4*)&Bs[buf][k][tn];
            float4 u1 = *(const float4*)&Bs[buf][k][tn + 4];
            br[0]=u0.x; br[1]=u0.y; br[2]=u0.z; br[3]=u0.w;
            br[4]=u1.x; br[5]=u1.y; br[6]=u1.z; br[7]=u1.w;
            #pragma unroll
            for (int i = 0; i < 8; i++)
                #pragma unroll
                for (int j = 0; j < 8; j++)
                    acc[i][j] = fmaf(ar[i], br[j], acc[i][j]);
        }

        if (kt + 1 < NT) {
            int nb = buf ^ 1;
            As[nb][lc+0][lr] = pa0.x; As[nb][lc+1][lr] = pa0.y;
            As[nb][lc+2][lr] = pa0.z; As[nb][lc+3][lr] = pa0.w;
            As[nb][lc+0][lr+64] = pa1.x; As[nb][lc+1][lr+64] = pa1.y;
            As[nb][lc+2][lr+64] = pa1.z; As[nb][lc+3][lr+64] = pa1.w;
            Bs[nb][lc+0][lr] = pb0.x; Bs[nb][lc+1][lr] = pb0.y;
            Bs[nb][lc+2][lr] = pb0.z; Bs[nb][lc+3][lr] = pb0.w;
            Bs[nb][lc+0][lr+64] = pb1.x; Bs[nb][lc+1][lr+64] = pb1.y;
            Bs[nb][lc+2][lr+64] = pb1.z; Bs[nb][lc+3][lr+64] = pb1.w;
        }
        __syncthreads();
        buf ^= 1;
    }

    float bb[8];
    #pragma unroll
    for (int j = 0; j < 8; j++) bb[j] = bias[bn + tn + j];

    const float inv_bn = rsqrtf(1.f + 1e-5f);
    float gg[8], be[8];
    #pragma unroll
    for (int j = 0; j < 8; j++) { gg[j] = bn_g[bn + tn + j]; be[j] = bn_b[bn + tn + j]; }
    #pragma unroll
    for (int i = 0; i < 8; i++) {
        int m = bm + tm + i;
        int b = m / NTOK, tok = m - b * NTOK;
        #pragma unroll
        for (int j = 0; j < 8; j++) {
            float v = acc[i][j] + bb[j];
            v = fmaxf(v, 0.f) * inv_bn;
            v = v * gg[j] + be[j];
            Cc[((size_t)b * N + (bn + tn + j)) * NTOK + tok] = v;
        }
    }
}

// ---------------------------------------------------------------------------
// Tensor-core flash attention (tf32 mma for QK^T and P*V).
// hd=64, heads=8, nk=1568. Logits ~ +-2 => exp without max subtraction is
// safe; softmax = exp(s)/sum(exp(s)), row sums deferred to kernel end.
// Block: 4 warps x 32 queries = 128 queries. Grid: (13, B*NH=32).
// Key tiles of 64 (tail: 32). K smem as [key][d]; V transposed to Vt[d][key].
// Row stride 68 words -> fragment loads bank-conflict-free.
// Fused per-8-key-chunk pipeline: S-chunk mmas -> exp -> quad-shuffle
// permute (accum frag -> A frag) -> PV mmas. Keeps live S at 16 regs.
// ---------------------------------------------------------------------------
struct AttnRegs {
    uint32_t aQ[2][8][4];
    float o[2][8][4];
    float l[2][2];
};

template<int NTL>
__device__ __forceinline__ void attn_tile(
    AttnRegs& R, const uint32_t (*Ks)[68], const uint32_t (*Vt)[68],
    int qr, int qc, int lane)
{
    int owner_lo = (lane & ~3) | (qc >> 1);
    int owner_hi = owner_lo + 2;
    int odd = qc & 1;

    #pragma unroll
    for (int nt = 0; nt < NTL; nt++) {
        // ---- S chunk: 32 queries x 8 keys ----
        float s[2][4];
        #pragma unroll
        for (int mt = 0; mt < 2; mt++)
            #pragma unroll
            for (int e = 0; e < 4; e++) s[mt][e] = 0.f;

        uint32_t bK[8][2];
        #pragma unroll
        for (int ks = 0; ks < 8; ks++) {
            bK[ks][0] = Ks[nt * 8 + qr][ks * 8 + qc];
            bK[ks][1] = Ks[nt * 8 + qr][ks * 8 + qc + 4];
        }
        #pragma unroll
        for (int mt = 0; mt < 2; mt++)
            #pragma unroll
            for (int ks = 0; ks < 8; ks++)
                mma_tf32(s[mt], R.aQ[mt][ks], bK[ks]);

        // ---- P = exp(s/8), accumulate row sums, tf32-round in place ----
        #pragma unroll
        for (int mt = 0; mt < 2; mt++) {
            float p0 = __expf(s[mt][0] * 0.125f);
            float p1 = __expf(s[mt][1] * 0.125f);
            float p2 = __expf(s[mt][2] * 0.125f);
            float p3 = __expf(s[mt][3] * 0.125f);
            R.l[mt][0] += p0 + p1;
            R.l[mt][1] += p2 + p3;
            s[mt][0] = __uint_as_float(f2tf32(p0));
            s[mt][1] = __uint_as_float(f2tf32(p1));
            s[mt][2] = __uint_as_float(f2tf32(p2));
            s[mt][3] = __uint_as_float(f2tf32(p3));
        }

        // ---- Permute accum frags -> A frags ----
        uint32_t aP[2][4];
        #pragma unroll
        for (int mt = 0; mt < 2; mt++) {
            float t00 = __shfl_sync(0xffffffffu, s[mt][0], owner_lo);
            float t01 = __shfl_sync(0xffffffffu, s[mt][1], owner_lo);
            float t10 = __shfl_sync(0xffffffffu, s[mt][2], owner_lo);
            float t11 = __shfl_sync(0xffffffffu, s[mt][3], owner_lo);
            float u00 = __shfl_sync(0xffffffffu, s[mt][0], owner_hi);
            float u01 = __shfl_sync(0xffffffffu, s[mt][1], owner_hi);
            float u10 = __shfl_sync(0xffffffffu, s[mt][2], owner_hi);
            float u11 = __shfl_sync(0xffffffffu, s[mt][3], owner_hi);
            aP[mt][0] = __float_as_uint(odd ? t01 : t00);
            aP[mt][1] = __float_as_uint(odd ? t11 : t10);
            aP[mt][2] = __float_as_uint(odd ? u01 : u00);
            aP[mt][3] = __float_as_uint(odd ? u11 : u10);
        }

        // ---- O += P_chunk @ V_chunk ----
        #pragma unroll
        for (int ntd = 0; ntd < 8; ntd++) {
            uint32_t bV[2];
            bV[0] = Vt[ntd * 8 + qr][nt * 8 + qc];
            bV[1] = Vt[ntd * 8 + qr][nt * 8 + qc + 4];
            mma_tf32(R.o[0][ntd], aP[0], bV);
            mma_tf32(R.o[1][ntd], aP[1], bV);
        }
    }
}

__global__ __launch_bounds__(128, 2) void attn_mma_kernel(
    const float* __restrict__ Q, const float* __restrict__ K,
    const float* __restrict__ V, float* __restrict__ T)
{
    int bh = blockIdx.y;
    int b = bh >> 3, h = bh & 7;
    int wid = threadIdx.x >> 5, lane = threadIdx.x & 31;
    int qr = lane >> 2, qc = lane & 3;
    int q0 = blockIdx.x * 128 + wid * 32;   // this warp's 32 queries

    __shared__ uint32_t Ks[64][68];
    __shared__ uint32_t Vt[64][68];

    const float* Qb = Q + (size_t)b * NTOK * C_ + h * HD;
    const float* Kb = K + (size_t)b * NTOK * C_ + h * HD;
    const float* Vb = V + (size_t)b * NTOK * C_ + h * HD;

    AttnRegs R;
    #pragma unroll
    for (int mt = 0; mt < 2; mt++) {
        int r0 = q0 + mt * 16 + qr;
        int r1 = r0 + 8;
        int rr0 = r0 < NTOK ? r0 : NTOK - 1;
        int rr1 = r1 < NTOK ? r1 : NTOK - 1;
        #pragma unroll
        for (int ks = 0; ks < 8; ks++) {
            int c = ks * 8 + qc;
            R.aQ[mt][ks][0] = f2tf32(Qb[(size_t)rr0 * C_ + c]);
            R.aQ[mt][ks][1] = f2tf32(Qb[(size_t)rr1 * C_ + c]);
            R.aQ[mt][ks][2] = f2tf32(Qb[(size_t)rr0 * C_ + c + 4]);
            R.aQ[mt][ks][3] = f2tf32(Qb[(size_t)rr1 * C_ + c + 4]);
        }
    }
    #pragma unroll
    for (int mt = 0; mt < 2; mt++) {
        #pragma unroll
        for (int nt = 0; nt < 8; nt++)
            #pragma unroll
            for (int e = 0; e < 4; e++) R.o[mt][nt][e] = 0.f;
        R.l[mt][0] = 0.f; R.l[mt][1] = 0.f;
    }

    // 24 full 64-key tiles + one 32-key tail (1568 = 24*64 + 32)
    for (int kt = 0; kt < 25; kt++) {
        int kbase = kt * 64;
        int nk = (kt == 24) ? 32 : 64;
        if (kt > 0) __syncthreads();
        for (int idx = threadIdx.x; idx < nk * 16; idx += 128) {
            int row = idx >> 4;
            int c4 = (idx & 15) * 4;
            float4 kv = *(const float4*)(Kb + (size_t)(kbase + row) * C_ + c4);
            Ks[row][c4 + 0] = f2tf32(kv.x);
            Ks[row][c4 + 1] = f2tf32(kv.y);
            Ks[row][c4 + 2] = f2tf32(kv.z);
            Ks[row][c4 + 3] = f2tf32(kv.w);
            float4 vv = *(const float4*)(Vb + (size_t)(kbase + row) * C_ + c4);
            Vt[c4 + 0][row] = f2tf32(vv.x);
            Vt[c4 + 1][row] = f2tf32(vv.y);
            Vt[c4 + 2][row] = f2tf32(vv.z);
            Vt[c4 + 3][row] = f2tf32(vv.w);
        }
        __syncthreads();
        if (nk == 64) attn_tile<8>(R, Ks, Vt, qr, qc, lane);
        else          attn_tile<4>(R, Ks, Vt, qr, qc, lane);
    }

    // Finalize: quad-reduce row sums, normalize, residual-add store
    float* Tb = T + (size_t)b * NTOK * C_ + h * HD;
    #pragma unroll
    for (int mt = 0; mt < 2; mt++) {
        float l0 = R.l[mt][0];
        l0 += __shfl_xor_sync(0xffffffffu, l0, 1);
        l0 += __shfl_xor_sync(0xffffffffu, l0, 2);
        float l1 = R.l[mt][1];
        l1 += __shfl_xor_sync(0xffffffffu, l1, 1);
        l1 += __shfl_xor_sync(0xffffffffu, l1, 2);
        float inv0 = 1.f / l0, inv1 = 1.f / l1;
        int r0 = q0 + mt * 16 + qr;
        int r1 = r0 + 8;
        #pragma unroll
        for (int ntd = 0; ntd < 8; ntd++) {
            int col = ntd * 8 + qc * 2;
            if (r0 < NTOK) {
                float2* p = (float2*)(Tb + (size_t)r0 * C_ + col);
                float2 old = *p;
                old.x += R.o[mt][ntd][0] * inv0;
                old.y += R.o[mt][ntd][1] * inv0;
                *p = old;
            }
            if (r1 < NTOK) {
                float2* p = (float2*)(Tb + (size_t)r1 * C_ + col);
                float2 old = *p;
                old.x += R.o[mt][ntd][2] * inv1;
                old.y += R.o[mt][ntd][3] * inv1;
                *p = old;
            }
        }
    }
}

// ---------------------------------------------------------------------------
// Host launcher
// ---------------------------------------------------------------------------
extern "C" void kernel_launch(void* const* d_in, const int* in_sizes, int n_in,
                              void* d_out, int out_size) {
    const float* x1    = (const float*)d_in[0];
    const float* x2    = (const float*)d_in[1];
    const float* Wq1   = (const float*)d_in[2];
    const float* bq1   = (const float*)d_in[3];
    const float* Wk1   = (const float*)d_in[4];
    const float* bk1   = (const float*)d_in[5];
    const float* Wv1   = (const float*)d_in[6];
    const float* bv1   = (const float*)d_in[7];
    const float* ln1_g = (const float*)d_in[8];
    const float* ln1_b = (const float*)d_in[9];
    const float* Wq2   = (const float*)d_in[10];
    const float* bq2   = (const float*)d_in[11];
    const float* Wk2   = (const float*)d_in[12];
    const float* bk2   = (const float*)d_in[13];
    const float* Wv2   = (const float*)d_in[14];
    const float* bv2   = (const float*)d_in[15];
    const float* ln2_g = (const float*)d_in[16];
    const float* ln2_b = (const float*)d_in[17];
    const float* o1w   = (const float*)d_in[18];
    const float* o1b   = (const float*)d_in[19];
    const float* bn1g  = (const float*)d_in[20];
    const float* bn1b  = (const float*)d_in[21];
    const float* o2w   = (const float*)d_in[22];
    const float* o2b   = (const float*)d_in[23];
    const float* bn2g  = (const float*)d_in[24];
    const float* bn2b  = (const float*)d_in[25];
    float* out = (float*)d_out;

    float* S = nullptr;
    cudaGetSymbolAddress((void**)&S, g_scratch);
    const size_t SZ = (size_t)M_ALL * C_;
    float* t1  = S + 0 * SZ;
    float* t2  = S + 1 * SZ;
    float* ln1 = S + 2 * SZ;
    float* ln2 = S + 3 * SZ;
    float* q1  = S + 4 * SZ;
    float* k1  = S + 5 * SZ;
    float* v1  = S + 6 * SZ;
    float* q2  = S + 7 * SZ;
    float* k2  = S + 8 * SZ;
    float* v2  = S + 9 * SZ;

    dim3 tokg(NTOK / 32, C_ / 32, B_), tokb(32, 8);
    tok_kernel<<<tokg, tokb>>>(x1, t1);
    tok_kernel<<<tokg, tokb>>>(x2, t2);

    dim3 gg(C_ / 128, M_ALL / 128);      // (4, 49)
    dim3 ag(13, B_ * NH);                // attn: 13 q-blocks x 32 (b,h)

    for (int i = 0; i < 3; i++) {
        size_t wo = (size_t)i * C_ * C_;
        size_t bo = (size_t)i * C_;
        ln_kernel<<<M_ALL, 128>>>(t1, ln1_g + bo, ln1_b + bo, ln1);
        ln_kernel<<<M_ALL, 128>>>(t2, ln2_g + bo, ln2_b + bo, ln2);
        gemm_tf32_kernel<<<gg, 256>>>(ln1, Wq1 + wo, bq1 + bo, q1);
        gemm_tf32_kernel<<<gg, 256>>>(t2,  Wk1 + wo, bk1 + bo, k1);
        gemm_tf32_kernel<<<gg, 256>>>(t2,  Wv1 + wo, bv1 + bo, v1);
        gemm_tf32_kernel<<<gg, 256>>>(ln2, Wq2 + wo, bq2 + bo, q2);
        gemm_tf32_kernel<<<gg, 256>>>(t1,  Wk2 + wo, bk2 + bo, k2);
        gemm_tf32_kernel<<<gg, 256>>>(t1,  Wv2 + wo, bv2 + bo, v2);
        attn_mma_kernel<<<ag, 128>>>(q1, k1, v1, t1);
        attn_mma_kernel<<<ag, 128>>>(q2, k2, v2, t2);
    }

    gemm_kernel<<<gg, 256>>>(t1, o1w, o1b, out,                          bn1g, bn1b);
    gemm_kernel<<<gg, 256>>>(t2, o2w, o2b, out + (size_t)B_ * C_ * NTOK, bn2g, bn2b);

    (void)in_sizes; (void)n_in; (void)out_size;
}

// round 9
// speedup vs baseline: 2.8223x; 1.1099x over previous
#include <cuda_runtime.h>
#include <math.h>
#include <stdint.h>

// Problem constants
#define B_    4
#define NTOK  1568
#define C_    512
#define NH    8
#define HD    64
#define M_ALL (B_*NTOK)   // 6272

// One big scratch buffer: 10 planes of [6272, 512] floats = 128.45 MB
__device__ float g_scratch[10ull * M_ALL * C_];

__device__ __forceinline__ uint32_t f2tf32(float f) {
    uint32_t u;
    asm("cvt.rna.tf32.f32 %0, %1;" : "=r"(u) : "f"(f));
    return u;
}

__device__ __forceinline__ void mma_tf32(float d[4], const uint32_t a[4], const uint32_t b[2]) {
    asm volatile(
        "mma.sync.aligned.m16n8k8.row.col.f32.tf32.tf32.f32 "
        "{%0,%1,%2,%3}, {%4,%5,%6,%7}, {%8,%9}, {%0,%1,%2,%3};\n"
        : "+f"(d[0]), "+f"(d[1]), "+f"(d[2]), "+f"(d[3])
        : "r"(a[0]), "r"(a[1]), "r"(a[2]), "r"(a[3]),
          "r"(b[0]), "r"(b[1]));
}

// Pointer-batch structs (passed by value as kernel args)
struct P6 { const float* A[6]; const float* W[6]; const float* bs[6]; float* C[6]; };
struct P2 { const float* A[2]; const float* W[2]; const float* bs[2];
            const float* g[2]; const float* be[2]; float* C[2]; };
struct A2 { const float* Q[2]; const float* K[2]; const float* V[2]; float* T[2]; };
struct L2 { const float* X[2]; const float* g[2]; const float* b[2]; float* Y[2]; };

// ---------------------------------------------------------------------------
// Tokenize: x [B, C, N] -> t [B, N, C]  (N = T*H*W = 1568)
// ---------------------------------------------------------------------------
__global__ void tok_kernel(const float* __restrict__ x, float* __restrict__ t) {
    __shared__ float tile[32][33];
    int b = blockIdx.z;
    int n0 = blockIdx.x * 32;
    int c0 = blockIdx.y * 32;
    const float* xb = x + (size_t)b * C_ * NTOK;
    float* tb = t + (size_t)b * NTOK * C_;
    int tx = threadIdx.x, ty = threadIdx.y;   // 32 x 8
    #pragma unroll
    for (int i = ty; i < 32; i += 8) {
        int c = c0 + i, n = n0 + tx;
        tile[i][tx] = xb[(size_t)c * NTOK + n];
    }
    __syncthreads();
    #pragma unroll
    for (int i = ty; i < 32; i += 8) {
        int n = n0 + i, c = c0 + tx;
        tb[(size_t)n * C_ + c] = tile[tx][i];
    }
}

// ---------------------------------------------------------------------------
// Batched LayerNorm: both streams in one launch. grid (6272, 2), block 128.
// ---------------------------------------------------------------------------
__global__ void ln_kernel(L2 p) {
    int z = blockIdx.y;
    int row = blockIdx.x;
    const float* x = p.X[z] + (size_t)row * C_;
    float* y = p.Y[z] + (size_t)row * C_;
    int tid = threadIdx.x;
    int lane = tid & 31, wid = tid >> 5;

    float4 v = *(const float4*)(x + tid * 4);
    float s  = v.x + v.y + v.z + v.w;
    float s2 = v.x*v.x + v.y*v.y + v.z*v.z + v.w*v.w;

    #pragma unroll
    for (int off = 16; off; off >>= 1) {
        s  += __shfl_xor_sync(0xffffffffu, s,  off);
        s2 += __shfl_xor_sync(0xffffffffu, s2, off);
    }
    __shared__ float smS[4], smS2[4];
    __shared__ float mu_s, rs_s;
    if (lane == 0) { smS[wid] = s; smS2[wid] = s2; }
    __syncthreads();
    if (tid == 0) {
        float S1 = smS[0] + smS[1] + smS[2] + smS[3];
        float S2 = smS2[0] + smS2[1] + smS2[2] + smS2[3];
        float mu = S1 * (1.f / C_);
        float var = S2 * (1.f / C_) - mu * mu;
        mu_s = mu;
        rs_s = rsqrtf(var + 1e-5f);
    }
    __syncthreads();
    float mu = mu_s, rs = rs_s;
    float4 gv = *(const float4*)(p.g[z] + tid * 4);
    float4 bv = *(const float4*)(p.b[z] + tid * 4);
    float4 o;
    o.x = (v.x - mu) * rs * gv.x + bv.x;
    o.y = (v.y - mu) * rs * gv.y + bv.y;
    o.z = (v.z - mu) * rs * gv.z + bv.z;
    o.w = (v.w - mu) * rs * gv.w + bv.w;
    *(float4*)(y + tid * 4) = o;
}

// ---------------------------------------------------------------------------
// Core tf32 mma 128x128x512 tile body. Computes d[4][4][4] for this thread's
// warp tile; A/B fetched via pointers. Shared by projection + out-head kernels.
// ---------------------------------------------------------------------------
__device__ __forceinline__ void gemm_tf32_body(
    const float* __restrict__ A, const float* __restrict__ Bw,
    int bm, int bn, float d[4][4][4],
    uint32_t (*As)[128][20], uint32_t (*Bs)[128][20])
{
    const int K = 512;
    int tid = threadIdx.x;
    int lr = tid >> 2;             // 0..63
    int lc = (tid & 3) << 2;       // 0,4,8,12
    const float* Ap = A  + (size_t)(bm + lr) * K + lc;
    const float* Bp = Bw + (size_t)(bn + lr) * K + lc;

    int wid = tid >> 5, lane = tid & 31;
    int wm = (wid & 1) * 64;
    int wn = (wid >> 1) * 32;
    int qr = lane >> 2;
    int qc = lane & 3;

    #pragma unroll
    for (int mi = 0; mi < 4; mi++)
        #pragma unroll
        for (int ni = 0; ni < 4; ni++)
            #pragma unroll
            for (int r = 0; r < 4; r++) d[mi][ni][r] = 0.f;

    float4 pa0 = *(const float4*)(Ap);
    float4 pa1 = *(const float4*)(Ap + (size_t)64 * K);
    float4 pb0 = *(const float4*)(Bp);
    float4 pb1 = *(const float4*)(Bp + (size_t)64 * K);

    As[0][lr   ][lc+0]=f2tf32(pa0.x); As[0][lr   ][lc+1]=f2tf32(pa0.y);
    As[0][lr   ][lc+2]=f2tf32(pa0.z); As[0][lr   ][lc+3]=f2tf32(pa0.w);
    As[0][lr+64][lc+0]=f2tf32(pa1.x); As[0][lr+64][lc+1]=f2tf32(pa1.y);
    As[0][lr+64][lc+2]=f2tf32(pa1.z); As[0][lr+64][lc+3]=f2tf32(pa1.w);
    Bs[0][lr   ][lc+0]=f2tf32(pb0.x); Bs[0][lr   ][lc+1]=f2tf32(pb0.y);
    Bs[0][lr   ][lc+2]=f2tf32(pb0.z); Bs[0][lr   ][lc+3]=f2tf32(pb0.w);
    Bs[0][lr+64][lc+0]=f2tf32(pb1.x); Bs[0][lr+64][lc+1]=f2tf32(pb1.y);
    Bs[0][lr+64][lc+2]=f2tf32(pb1.z); Bs[0][lr+64][lc+3]=f2tf32(pb1.w);
    __syncthreads();

    const int NT = K / 16;
    int buf = 0;
    for (int kt = 0; kt < NT; kt++) {
        if (kt + 1 < NT) {
            int k0 = (kt + 1) * 16;
            pa0 = *(const float4*)(Ap + k0);
            pa1 = *(const float4*)(Ap + (size_t)64 * K + k0);
            pb0 = *(const float4*)(Bp + k0);
            pb1 = *(const float4*)(Bp + (size_t)64 * K + k0);
        }

        #pragma unroll
        for (int ks = 0; ks < 2; ks++) {
            int k0 = ks * 8;
            uint32_t a[4][4], bfr[4][2];
            #pragma unroll
            for (int mi = 0; mi < 4; mi++) {
                int r0 = wm + mi * 16 + qr;
                a[mi][0] = As[buf][r0    ][k0 + qc];
                a[mi][1] = As[buf][r0 + 8][k0 + qc];
                a[mi][2] = As[buf][r0    ][k0 + qc + 4];
                a[mi][3] = As[buf][r0 + 8][k0 + qc + 4];
            }
            #pragma unroll
            for (int ni = 0; ni < 4; ni++) {
                int c0 = wn + ni * 8 + qr;
                bfr[ni][0] = Bs[buf][c0][k0 + qc];
                bfr[ni][1] = Bs[buf][c0][k0 + qc + 4];
            }
            #pragma unroll
            for (int mi = 0; mi < 4; mi++)
                #pragma unroll
                for (int ni = 0; ni < 4; ni++)
                    mma_tf32(d[mi][ni], a[mi], bfr[ni]);
        }

        if (kt + 1 < NT) {
            int nb = buf ^ 1;
            As[nb][lr   ][lc+0]=f2tf32(pa0.x); As[nb][lr   ][lc+1]=f2tf32(pa0.y);
            As[nb][lr   ][lc+2]=f2tf32(pa0.z); As[nb][lr   ][lc+3]=f2tf32(pa0.w);
            As[nb][lr+64][lc+0]=f2tf32(pa1.x); As[nb][lr+64][lc+1]=f2tf32(pa1.y);
            As[nb][lr+64][lc+2]=f2tf32(pa1.z); As[nb][lr+64][lc+3]=f2tf32(pa1.w);
            Bs[nb][lr   ][lc+0]=f2tf32(pb0.x); Bs[nb][lr   ][lc+1]=f2tf32(pb0.y);
            Bs[nb][lr   ][lc+2]=f2tf32(pb0.z); Bs[nb][lr   ][lc+3]=f2tf32(pb0.w);
            Bs[nb][lr+64][lc+0]=f2tf32(pb1.x); Bs[nb][lr+64][lc+1]=f2tf32(pb1.y);
            Bs[nb][lr+64][lc+2]=f2tf32(pb1.z); Bs[nb][lr+64][lc+3]=f2tf32(pb1.w);
        }
        __syncthreads();
        buf ^= 1;
    }
}

// ---------------------------------------------------------------------------
// Batched projection GEMM: 6 independent [6272,512]x[512,512]^T per launch.
// grid (4, 49, 6), block 256.
// ---------------------------------------------------------------------------
__global__ __launch_bounds__(256) void gemm_proj_kernel(P6 p) {
    __shared__ uint32_t As[2][128][20];
    __shared__ uint32_t Bs[2][128][20];
    int gz = blockIdx.z;
    int bm = blockIdx.y * 128;
    int bn = blockIdx.x * 128;

    float d[4][4][4];
    gemm_tf32_body(p.A[gz], p.W[gz], bm, bn, d, As, Bs);

    int tid = threadIdx.x;
    int wid = tid >> 5, lane = tid & 31;
    int wm = (wid & 1) * 64, wn = (wid >> 1) * 32;
    int qr = lane >> 2, qc = lane & 3;
    const float* bias = p.bs[gz];
    float* Cc = p.C[gz];

    #pragma unroll
    for (int mi = 0; mi < 4; mi++) {
        int row0 = bm + wm + mi * 16 + qr;
        #pragma unroll
        for (int ni = 0; ni < 4; ni++) {
            int col0 = bn + wn + ni * 8 + qc * 2;
            float b0 = bias[col0], b1 = bias[col0 + 1];
            float2 v0 = make_float2(d[mi][ni][0] + b0, d[mi][ni][1] + b1);
            float2 v1 = make_float2(d[mi][ni][2] + b0, d[mi][ni][3] + b1);
            *(float2*)(Cc + (size_t)row0 * C_ + col0)       = v0;
            *(float2*)(Cc + (size_t)(row0 + 8) * C_ + col0) = v1;
        }
    }
}

// ---------------------------------------------------------------------------
// Batched output head (tf32): z = relu(t@W^T + b) * rsqrt(1+eps) * g + be,
// stored transposed per batch: out[(b*512 + col)*1568 + tok].
// grid (4, 49, 2), block 256.
// ---------------------------------------------------------------------------
__global__ __launch_bounds__(256) void gemm_out_kernel(P2 p) {
    __shared__ uint32_t As[2][128][20];
    __shared__ uint32_t Bs[2][128][20];
    int gz = blockIdx.z;
    int bm = blockIdx.y * 128;
    int bn = blockIdx.x * 128;

    float d[4][4][4];
    gemm_tf32_body(p.A[gz], p.W[gz], bm, bn, d, As, Bs);

    int tid = threadIdx.x;
    int wid = tid >> 5, lane = tid & 31;
    int wm = (wid & 1) * 64, wn = (wid >> 1) * 32;
    int qr = lane >> 2, qc = lane & 3;
    const float* bias = p.bs[gz];
    const float* bng  = p.g[gz];
    const float* bnb  = p.be[gz];
    float* Cc = p.C[gz];
    const float inv_bn = rsqrtf(1.f + 1e-5f);

    #pragma unroll
    for (int mi = 0; mi < 4; mi++) {
        int m0 = bm + wm + mi * 16 + qr;     // token rows m0, m0+8
        int b0i = m0 / NTOK, tok0 = m0 - b0i * NTOK;
        int m1 = m0 + 8;
        int b1i = m1 / NTOK, tok1 = m1 - b1i * NTOK;
        #pragma unroll
        for (int ni = 0; ni < 4; ni++) {
            int col0 = bn + wn + ni * 8 + qc * 2;
            #pragma unroll
            for (int e = 0; e < 2; e++) {
                int col = col0 + e;
                float bb = bias[col], gg = bng[col], be = bnb[col];
                float v0 = fmaxf(d[mi][ni][e] + bb, 0.f) * inv_bn * gg + be;
                float v1 = fmaxf(d[mi][ni][2 + e] + bb, 0.f) * inv_bn * gg + be;
                Cc[((size_t)b0i * C_ + col) * NTOK + tok0] = v0;
                Cc[((size_t)b1i * C_ + col) * NTOK + tok1] = v1;
            }
        }
    }
}

// ---------------------------------------------------------------------------
// Tensor-core flash attention (tf32 mma for QK^T and P*V), batched x2.
// Block: 4 warps x 32 queries = 128 queries. Grid: (13, 32, 2).
// ---------------------------------------------------------------------------
struct AttnRegs {
    uint32_t aQ[2][8][4];
    float o[2][8][4];
    float l[2][2];
};

template<int NTL>
__device__ __forceinline__ void attn_tile(
    AttnRegs& R, const uint32_t (*Ks)[68], const uint32_t (*Vt)[68],
    int qr, int qc, int lane)
{
    int owner_lo = (lane & ~3) | (qc >> 1);
    int owner_hi = owner_lo + 2;
    int odd = qc & 1;

    #pragma unroll
    for (int nt = 0; nt < NTL; nt++) {
        float s[2][4];
        #pragma unroll
        for (int mt = 0; mt < 2; mt++)
            #pragma unroll
            for (int e = 0; e < 4; e++) s[mt][e] = 0.f;

        uint32_t bK[8][2];
        #pragma unroll
        for (int ks = 0; ks < 8; ks++) {
            bK[ks][0] = Ks[nt * 8 + qr][ks * 8 + qc];
            bK[ks][1] = Ks[nt * 8 + qr][ks * 8 + qc + 4];
        }
        #pragma unroll
        for (int mt = 0; mt < 2; mt++)
            #pragma unroll
            for (int ks = 0; ks < 8; ks++)
                mma_tf32(s[mt], R.aQ[mt][ks], bK[ks]);

        #pragma unroll
        for (int mt = 0; mt < 2; mt++) {
            float p0 = __expf(s[mt][0] * 0.125f);
            float p1 = __expf(s[mt][1] * 0.125f);
            float p2 = __expf(s[mt][2] * 0.125f);
            float p3 = __expf(s[mt][3] * 0.125f);
            R.l[mt][0] += p0 + p1;
            R.l[mt][1] += p2 + p3;
            s[mt][0] = __uint_as_float(f2tf32(p0));
            s[mt][1] = __uint_as_float(f2tf32(p1));
            s[mt][2] = __uint_as_float(f2tf32(p2));
            s[mt][3] = __uint_as_float(f2tf32(p3));
        }

        uint32_t aP[2][4];
        #pragma unroll
        for (int mt = 0; mt < 2; mt++) {
            float t00 = __shfl_sync(0xffffffffu, s[mt][0], owner_lo);
            float t01 = __shfl_sync(0xffffffffu, s[mt][1], owner_lo);
            float t10 = __shfl_sync(0xffffffffu, s[mt][2], owner_lo);
            float t11 = __shfl_sync(0xffffffffu, s[mt][3], owner_lo);
            float u00 = __shfl_sync(0xffffffffu, s[mt][0], owner_hi);
            float u01 = __shfl_sync(0xffffffffu, s[mt][1], owner_hi);
            float u10 = __shfl_sync(0xffffffffu, s[mt][2], owner_hi);
            float u11 = __shfl_sync(0xffffffffu, s[mt][3], owner_hi);
            aP[mt][0] = __float_as_uint(odd ? t01 : t00);
            aP[mt][1] = __float_as_uint(odd ? t11 : t10);
            aP[mt][2] = __float_as_uint(odd ? u01 : u00);
            aP[mt][3] = __float_as_uint(odd ? u11 : u10);
        }

        #pragma unroll
        for (int ntd = 0; ntd < 8; ntd++) {
            uint32_t bV[2];
            bV[0] = Vt[ntd * 8 + qr][nt * 8 + qc];
            bV[1] = Vt[ntd * 8 + qr][nt * 8 + qc + 4];
            mma_tf32(R.o[0][ntd], aP[0], bV);
            mma_tf32(R.o[1][ntd], aP[1], bV);
        }
    }
}

__global__ __launch_bounds__(128, 2) void attn_mma_kernel(A2 p) {
    int gz = blockIdx.z;
    int bh = blockIdx.y;
    int b = bh >> 3, h = bh & 7;
    int wid = threadIdx.x >> 5, lane = threadIdx.x & 31;
    int qr = lane >> 2, qc = lane & 3;
    int q0 = blockIdx.x * 128 + wid * 32;

    __shared__ uint32_t Ks[64][68];
    __shared__ uint32_t Vt[64][68];

    const float* Qb = p.Q[gz] + (size_t)b * NTOK * C_ + h * HD;
    const float* Kb = p.K[gz] + (size_t)b * NTOK * C_ + h * HD;
    const float* Vb = p.V[gz] + (size_t)b * NTOK * C_ + h * HD;

    AttnRegs R;
    #pragma unroll
    for (int mt = 0; mt < 2; mt++) {
        int r0 = q0 + mt * 16 + qr;
        int r1 = r0 + 8;
        int rr0 = r0 < NTOK ? r0 : NTOK - 1;
        int rr1 = r1 < NTOK ? r1 : NTOK - 1;
        #pragma unroll
        for (int ks = 0; ks < 8; ks++) {
            int c = ks * 8 + qc;
            R.aQ[mt][ks][0] = f2tf32(Qb[(size_t)rr0 * C_ + c]);
            R.aQ[mt][ks][1] = f2tf32(Qb[(size_t)rr1 * C_ + c]);
            R.aQ[mt][ks][2] = f2tf32(Qb[(size_t)rr0 * C_ + c + 4]);
            R.aQ[mt][ks][3] = f2tf32(Qb[(size_t)rr1 * C_ + c + 4]);
        }
    }
    #pragma unroll
    for (int mt = 0; mt < 2; mt++) {
        #pragma unroll
        for (int nt = 0; nt < 8; nt++)
            #pragma unroll
            for (int e = 0; e < 4; e++) R.o[mt][nt][e] = 0.f;
        R.l[mt][0] = 0.f; R.l[mt][1] = 0.f;
    }

    // 24 full 64-key tiles + one 32-key tail (1568 = 24*64 + 32)
    for (int kt = 0; kt < 25; kt++) {
        int kbase = kt * 64;
        int nk = (kt == 24) ? 32 : 64;
        if (kt > 0) __syncthreads();
        for (int idx = threadIdx.x; idx < nk * 16; idx += 128) {
            int row = idx >> 4;
            int c4 = (idx & 15) * 4;
            float4 kv = *(const float4*)(Kb + (size_t)(kbase + row) * C_ + c4);
            Ks[row][c4 + 0] = f2tf32(kv.x);
            Ks[row][c4 + 1] = f2tf32(kv.y);
            Ks[row][c4 + 2] = f2tf32(kv.z);
            Ks[row][c4 + 3] = f2tf32(kv.w);
            float4 vv = *(const float4*)(Vb + (size_t)(kbase + row) * C_ + c4);
            Vt[c4 + 0][row] = f2tf32(vv.x);
            Vt[c4 + 1][row] = f2tf32(vv.y);
            Vt[c4 + 2][row] = f2tf32(vv.z);
            Vt[c4 + 3][row] = f2tf32(vv.w);
        }
        __syncthreads();
        if (nk == 64) attn_tile<8>(R, Ks, Vt, qr, qc, lane);
        else          attn_tile<4>(R, Ks, Vt, qr, qc, lane);
    }

    // Finalize: quad-reduce row sums, normalize, residual-add store
    float* Tb = p.T[gz] + (size_t)b * NTOK * C_ + h * HD;
    #pragma unroll
    for (int mt = 0; mt < 2; mt++) {
        float l0 = R.l[mt][0];
        l0 += __shfl_xor_sync(0xffffffffu, l0, 1);
        l0 += __shfl_xor_sync(0xffffffffu, l0, 2);
        float l1 = R.l[mt][1];
        l1 += __shfl_xor_sync(0xffffffffu, l1, 1);
        l1 += __shfl_xor_sync(0xffffffffu, l1, 2);
        float inv0 = 1.f / l0, inv1 = 1.f / l1;
        int r0 = q0 + mt * 16 + qr;
        int r1 = r0 + 8;
        #pragma unroll
        for (int ntd = 0; ntd < 8; ntd++) {
            int col = ntd * 8 + qc * 2;
            if (r0 < NTOK) {
                float2* pp = (float2*)(Tb + (size_t)r0 * C_ + col);
                float2 old = *pp;
                old.x += R.o[mt][ntd][0] * inv0;
                old.y += R.o[mt][ntd][1] * inv0;
                *pp = old;
            }
            if (r1 < NTOK) {
                float2* pp = (float2*)(Tb + (size_t)r1 * C_ + col);
                float2 old = *pp;
                old.x += R.o[mt][ntd][2] * inv1;
                old.y += R.o[mt][ntd][3] * inv1;
                *pp = old;
            }
        }
    }
}

// ---------------------------------------------------------------------------
// Host launcher
// ---------------------------------------------------------------------------
extern "C" void kernel_launch(void* const* d_in, const int* in_sizes, int n_in,
                              void* d_out, int out_size) {
    const float* x1    = (const float*)d_in[0];
    const float* x2    = (const float*)d_in[1];
    const float* Wq1   = (const float*)d_in[2];
    const float* bq1   = (const float*)d_in[3];
    const float* Wk1   = (const float*)d_in[4];
    const float* bk1   = (const float*)d_in[5];
    const float* Wv1   = (const float*)d_in[6];
    const float* bv1   = (const float*)d_in[7];
    const float* ln1_g = (const float*)d_in[8];
    const float* ln1_b = (const float*)d_in[9];
    const float* Wq2   = (const float*)d_in[10];
    const float* bq2   = (const float*)d_in[11];
    const float* Wk2   = (const float*)d_in[12];
    const float* bk2   = (const float*)d_in[13];
    const float* Wv2   = (const float*)d_in[14];
    const float* bv2   = (const float*)d_in[15];
    const float* ln2_g = (const float*)d_in[16];
    const float* ln2_b = (const float*)d_in[17];
    const float* o1w   = (const float*)d_in[18];
    const float* o1b   = (const float*)d_in[19];
    const float* bn1g  = (const float*)d_in[20];
    const float* bn1b  = (const float*)d_in[21];
    const float* o2w   = (const float*)d_in[22];
    const float* o2b   = (const float*)d_in[23];
    const float* bn2g  = (const float*)d_in[24];
    const float* bn2b  = (const float*)d_in[25];
    float* out = (float*)d_out;

    float* S = nullptr;
    cudaGetSymbolAddress((void**)&S, g_scratch);
    const size_t SZ = (size_t)M_ALL * C_;
    float* t1  = S + 0 * SZ;
    float* t2  = S + 1 * SZ;
    float* ln1 = S + 2 * SZ;
    float* ln2 = S + 3 * SZ;
    float* q1  = S + 4 * SZ;
    float* k1  = S + 5 * SZ;
    float* v1  = S + 6 * SZ;
    float* q2  = S + 7 * SZ;
    float* k2  = S + 8 * SZ;
    float* v2  = S + 9 * SZ;

    dim3 tokg(NTOK / 32, C_ / 32, B_), tokb(32, 8);
    tok_kernel<<<tokg, tokb>>>(x1, t1);
    tok_kernel<<<tokg, tokb>>>(x2, t2);

    dim3 lng(M_ALL, 2);
    dim3 gg(C_ / 128, M_ALL / 128, 6);   // (4, 49, 6)
    dim3 og(C_ / 128, M_ALL / 128, 2);   // (4, 49, 2)
    dim3 ag(13, B_ * NH, 2);             // (13, 32, 2)

    for (int i = 0; i < 3; i++) {
        size_t wo = (size_t)i * C_ * C_;
        size_t bo = (size_t)i * C_;

        L2 lp;
        lp.X[0] = t1; lp.g[0] = ln1_g + bo; lp.b[0] = ln1_b + bo; lp.Y[0] = ln1;
        lp.X[1] = t2; lp.g[1] = ln2_g + bo; lp.b[1] = ln2_b + bo; lp.Y[1] = ln2;
        ln_kernel<<<lng, 128>>>(lp);

        P6 gp;
        gp.A[0] = ln1; gp.W[0] = Wq1 + wo; gp.bs[0] = bq1 + bo; gp.C[0] = q1;
        gp.A[1] = t2;  gp.W[1] = Wk1 + wo; gp.bs[1] = bk1 + bo; gp.C[1] = k1;
        gp.A[2] = t2;  gp.W[2] = Wv1 + wo; gp.bs[2] = bv1 + bo; gp.C[2] = v1;
        gp.A[3] = ln2; gp.W[3] = Wq2 + wo; gp.bs[3] = bq2 + bo; gp.C[3] = q2;
        gp.A[4] = t1;  gp.W[4] = Wk2 + wo; gp.bs[4] = bk2 + bo; gp.C[4] = k2;
        gp.A[5] = t1;  gp.W[5] = Wv2 + wo; gp.bs[5] = bv2 + bo; gp.C[5] = v2;
        gemm_proj_kernel<<<gg, 256>>>(gp);

        A2 ap;
        ap.Q[0] = q1; ap.K[0] = k1; ap.V[0] = v1; ap.T[0] = t1;
        ap.Q[1] = q2; ap.K[1] = k2; ap.V[1] = v2; ap.T[1] = t2;
        attn_mma_kernel<<<ag, 128>>>(ap);
    }

    P2 op;
    op.A[0] = t1; op.W[0] = o1w; op.bs[0] = o1b; op.g[0] = bn1g; op.be[0] = bn1b;
    op.C[0] = out;
    op.A[1] = t2; op.W[1] = o2w; op.bs[1] = o2b; op.g[1] = bn2g; op.be[1] = bn2b;
    op.C[1] = out + (size_t)B_ * C_ * NTOK;
    gemm_out_kernel<<<og, 256>>>(op);

    (void)in_sizes; (void)n_in; (void)out_size;
}

// round 13
// speedup vs baseline: 2.9541x; 1.0467x over previous
#include <cuda_runtime.h>
#include <math.h>
#include <stdint.h>

// Problem constants
#define B_    4
#define NTOK  1568
#define C_    512
#define NH    8
#define HD    64
#define M_ALL (B_*NTOK)   // 6272

// One big scratch buffer: 10 planes of [6272, 512] floats = 128.45 MB
__device__ float g_scratch[10ull * M_ALL * C_];

__device__ __forceinline__ uint32_t f2tf32(float f) {
    uint32_t u;
    asm("cvt.rna.tf32.f32 %0, %1;" : "=r"(u) : "f"(f));
    return u;
}

__device__ __forceinline__ void mma_tf32(float d[4], const uint32_t a[4], const uint32_t b[2]) {
    asm volatile(
        "mma.sync.aligned.m16n8k8.row.col.f32.tf32.tf32.f32 "
        "{%0,%1,%2,%3}, {%4,%5,%6,%7}, {%8,%9}, {%0,%1,%2,%3};\n"
        : "+f"(d[0]), "+f"(d[1]), "+f"(d[2]), "+f"(d[3])
        : "r"(a[0]), "r"(a[1]), "r"(a[2]), "r"(a[3]),
          "r"(b[0]), "r"(b[1]));
}

__device__ __forceinline__ void ldsm_x4(uint32_t& r0, uint32_t& r1, uint32_t& r2, uint32_t& r3,
                                        uint32_t addr) {
    asm volatile("ldmatrix.sync.aligned.m8n8.x4.shared.b16 {%0,%1,%2,%3}, [%4];"
        : "=r"(r0), "=r"(r1), "=r"(r2), "=r"(r3) : "r"(addr));
}
__device__ __forceinline__ void ldsm_x2(uint32_t& r0, uint32_t& r1, uint32_t addr) {
    asm volatile("ldmatrix.sync.aligned.m8n8.x2.shared.b16 {%0,%1}, [%2];"
        : "=r"(r0), "=r"(r1) : "r"(addr));
}
__device__ __forceinline__ uint32_t smem_u32(const void* p) {
    return (uint32_t)__cvta_generic_to_shared(p);
}

// Pointer-batch structs (passed by value as kernel args)
struct P6 { const float* A[6]; const float* W[6]; const float* bs[6]; float* C[6]; };
struct P2 { const float* A[2]; const float* W[2]; const float* bs[2];
            const float* g[2]; const float* be[2]; float* C[2]; };
struct A2 { const float* Q[2]; const float* K[2]; const float* V[2]; float* T[2]; };
struct L2 { const float* X[2]; const float* g[2]; const float* b[2]; float* Y[2]; };

// ---------------------------------------------------------------------------
// Tokenize: x [B, C, N] -> t [B, N, C]
// ---------------------------------------------------------------------------
__global__ void tok_kernel(const float* __restrict__ x, float* __restrict__ t) {
    __shared__ float tile[32][33];
    int b = blockIdx.z;
    int n0 = blockIdx.x * 32;
    int c0 = blockIdx.y * 32;
    const float* xb = x + (size_t)b * C_ * NTOK;
    float* tb = t + (size_t)b * NTOK * C_;
    int tx = threadIdx.x, ty = threadIdx.y;   // 32 x 8
    #pragma unroll
    for (int i = ty; i < 32; i += 8) {
        int c = c0 + i, n = n0 + tx;
        tile[i][tx] = xb[(size_t)c * NTOK + n];
    }
    __syncthreads();
    #pragma unroll
    for (int i = ty; i < 32; i += 8) {
        int n = n0 + i, c = c0 + tx;
        tb[(size_t)n * C_ + c] = tile[tx][i];
    }
}

// ---------------------------------------------------------------------------
// Batched LayerNorm: grid (6272, 2), block 128.
// ---------------------------------------------------------------------------
__global__ void ln_kernel(L2 p) {
    int z = blockIdx.y;
    int row = blockIdx.x;
    const float* x = p.X[z] + (size_t)row * C_;
    float* y = p.Y[z] + (size_t)row * C_;
    int tid = threadIdx.x;
    int lane = tid & 31, wid = tid >> 5;

    float4 v = *(const float4*)(x + tid * 4);
    float s  = v.x + v.y + v.z + v.w;
    float s2 = v.x*v.x + v.y*v.y + v.z*v.z + v.w*v.w;

    #pragma unroll
    for (int off = 16; off; off >>= 1) {
        s  += __shfl_xor_sync(0xffffffffu, s,  off);
        s2 += __shfl_xor_sync(0xffffffffu, s2, off);
    }
    __shared__ float smS[4], smS2[4];
    __shared__ float mu_s, rs_s;
    if (lane == 0) { smS[wid] = s; smS2[wid] = s2; }
    __syncthreads();
    if (tid == 0) {
        float S1 = smS[0] + smS[1] + smS[2] + smS[3];
        float S2 = smS2[0] + smS2[1] + smS2[2] + smS2[3];
        float mu = S1 * (1.f / C_);
        float var = S2 * (1.f / C_) - mu * mu;
        mu_s = mu;
        rs_s = rsqrtf(var + 1e-5f);
    }
    __syncthreads();
    float mu = mu_s, rs = rs_s;
    float4 gv = *(const float4*)(p.g[z] + tid * 4);
    float4 bv = *(const float4*)(p.b[z] + tid * 4);
    float4 o;
    o.x = (v.x - mu) * rs * gv.x + bv.x;
    o.y = (v.y - mu) * rs * gv.y + bv.y;
    o.z = (v.z - mu) * rs * gv.z + bv.z;
    o.w = (v.w - mu) * rs * gv.w + bv.w;
    *(float4*)(y + tid * 4) = o;
}

// ---------------------------------------------------------------------------
// Core tf32 mma 128x128x512 tile body. Fragment loads via ldmatrix:
//  A frag (m16k8): ldmatrix.x4 -- lanes 0-7 rows 0-7@k0, 8-15 rows 8-15@k0,
//                  16-23 rows 0-7@k0+4, 24-31 rows 8-15@k0+4.
//  B frag (n8k8):  ldmatrix.x2 -- lanes 0-7 rows@k0, 8-15 rows@k0+4.
// Smem stores vectorized to STS.128.
// ---------------------------------------------------------------------------
__device__ __forceinline__ void gemm_tf32_body(
    const float* __restrict__ A, const float* __restrict__ Bw,
    int bm, int bn, float d[4][4][4],
    uint32_t (*As)[128][20], uint32_t (*Bs)[128][20])
{
    const int K = 512;
    int tid = threadIdx.x;
    int lr = tid >> 2;             // 0..63
    int lc = (tid & 3) << 2;       // 0,4,8,12
    const float* Ap = A  + (size_t)(bm + lr) * K + lc;
    const float* Bp = Bw + (size_t)(bn + lr) * K + lc;

    int wid = tid >> 5, lane = tid & 31;
    int wm = (wid & 1) * 64;
    int wn = (wid >> 1) * 32;

    // ldmatrix lane address roles
    int a_row  = lane & 15;
    int a_koff = (lane >> 4) * 4;          // 0 or 4
    int b_row  = lane & 7;
    int b_koff = ((lane >> 3) & 1) * 4;    // 0 or 4

    #pragma unroll
    for (int mi = 0; mi < 4; mi++)
        #pragma unroll
        for (int ni = 0; ni < 4; ni++)
            #pragma unroll
            for (int r = 0; r < 4; r++) d[mi][ni][r] = 0.f;

    float4 pa0 = *(const float4*)(Ap);
    float4 pa1 = *(const float4*)(Ap + (size_t)64 * K);
    float4 pb0 = *(const float4*)(Bp);
    float4 pb1 = *(const float4*)(Bp + (size_t)64 * K);

    *(uint4*)&As[0][lr   ][lc] = make_uint4(f2tf32(pa0.x), f2tf32(pa0.y), f2tf32(pa0.z), f2tf32(pa0.w));
    *(uint4*)&As[0][lr+64][lc] = make_uint4(f2tf32(pa1.x), f2tf32(pa1.y), f2tf32(pa1.z), f2tf32(pa1.w));
    *(uint4*)&Bs[0][lr   ][lc] = make_uint4(f2tf32(pb0.x), f2tf32(pb0.y), f2tf32(pb0.z), f2tf32(pb0.w));
    *(uint4*)&Bs[0][lr+64][lc] = make_uint4(f2tf32(pb1.x), f2tf32(pb1.y), f2tf32(pb1.z), f2tf32(pb1.w));
    __syncthreads();

    const int NT = K / 16;
    int buf = 0;
    for (int kt = 0; kt < NT; kt++) {
        if (kt + 1 < NT) {
            int k0 = (kt + 1) * 16;
            pa0 = *(const float4*)(Ap + k0);
            pa1 = *(const float4*)(Ap + (size_t)64 * K + k0);
            pb0 = *(const float4*)(Bp + k0);
            pb1 = *(const float4*)(Bp + (size_t)64 * K + k0);
        }

        #pragma unroll
        for (int ks = 0; ks < 2; ks++) {
            int k0 = ks * 8;
            uint32_t a[4][4], bfr[4][2];
            #pragma unroll
            for (int mi = 0; mi < 4; mi++) {
                uint32_t ad = smem_u32(&As[buf][wm + mi * 16 + a_row][k0 + a_koff]);
                ldsm_x4(a[mi][0], a[mi][1], a[mi][2], a[mi][3], ad);
            }
            #pragma unroll
            for (int ni = 0; ni < 4; ni++) {
                uint32_t ad = smem_u32(&Bs[buf][wn + ni * 8 + b_row][k0 + b_koff]);
                ldsm_x2(bfr[ni][0], bfr[ni][1], ad);
            }
            #pragma unroll
            for (int mi = 0; mi < 4; mi++)
                #pragma unroll
                for (int ni = 0; ni < 4; ni++)
                    mma_tf32(d[mi][ni], a[mi], bfr[ni]);
        }

        if (kt + 1 < NT) {
            int nb = buf ^ 1;
            *(uint4*)&As[nb][lr   ][lc] = make_uint4(f2tf32(pa0.x), f2tf32(pa0.y), f2tf32(pa0.z), f2tf32(pa0.w));
            *(uint4*)&As[nb][lr+64][lc] = make_uint4(f2tf32(pa1.x), f2tf32(pa1.y), f2tf32(pa1.z), f2tf32(pa1.w));
            *(uint4*)&Bs[nb][lr   ][lc] = make_uint4(f2tf32(pb0.x), f2tf32(pb0.y), f2tf32(pb0.z), f2tf32(pb0.w));
            *(uint4*)&Bs[nb][lr+64][lc] = make_uint4(f2tf32(pb1.x), f2tf32(pb1.y), f2tf32(pb1.z), f2tf32(pb1.w));
        }
        __syncthreads();
        buf ^= 1;
    }
}

// ---------------------------------------------------------------------------
// Batched projection GEMM: grid (4, 49, 6), block 256.
// ---------------------------------------------------------------------------
__global__ __launch_bounds__(256) void gemm_proj_kernel(P6 p) {
    __shared__ __align__(16) uint32_t As[2][128][20];
    __shared__ __align__(16) uint32_t Bs[2][128][20];
    int gz = blockIdx.z;
    int bm = blockIdx.y * 128;
    int bn = blockIdx.x * 128;

    float d[4][4][4];
    gemm_tf32_body(p.A[gz], p.W[gz], bm, bn, d, As, Bs);

    int tid = threadIdx.x;
    int wid = tid >> 5, lane = tid & 31;
    int wm = (wid & 1) * 64, wn = (wid >> 1) * 32;
    int qr = lane >> 2, qc = lane & 3;
    const float* bias = p.bs[gz];
    float* Cc = p.C[gz];

    #pragma unroll
    for (int mi = 0; mi < 4; mi++) {
        int row0 = bm + wm + mi * 16 + qr;
        #pragma unroll
        for (int ni = 0; ni < 4; ni++) {
            int col0 = bn + wn + ni * 8 + qc * 2;
            float b0 = bias[col0], b1 = bias[col0 + 1];
            float2 v0 = make_float2(d[mi][ni][0] + b0, d[mi][ni][1] + b1);
            float2 v1 = make_float2(d[mi][ni][2] + b0, d[mi][ni][3] + b1);
            *(float2*)(Cc + (size_t)row0 * C_ + col0)       = v0;
            *(float2*)(Cc + (size_t)(row0 + 8) * C_ + col0) = v1;
        }
    }
}

// ---------------------------------------------------------------------------
// Batched output head (tf32): grid (4, 49, 2), block 256.
// ---------------------------------------------------------------------------
__global__ __launch_bounds__(256) void gemm_out_kernel(P2 p) {
    __shared__ __align__(16) uint32_t As[2][128][20];
    __shared__ __align__(16) uint32_t Bs[2][128][20];
    int gz = blockIdx.z;
    int bm = blockIdx.y * 128;
    int bn = blockIdx.x * 128;

    float d[4][4][4];
    gemm_tf32_body(p.A[gz], p.W[gz], bm, bn, d, As, Bs);

    int tid = threadIdx.x;
    int wid = tid >> 5, lane = tid & 31;
    int wm = (wid & 1) * 64, wn = (wid >> 1) * 32;
    int qr = lane >> 2, qc = lane & 3;
    const float* bias = p.bs[gz];
    const float* bng  = p.g[gz];
    const float* bnb  = p.be[gz];
    float* Cc = p.C[gz];
    const float inv_bn = rsqrtf(1.f + 1e-5f);

    #pragma unroll
    for (int mi = 0; mi < 4; mi++) {
        int m0 = bm + wm + mi * 16 + qr;
        int b0i = m0 / NTOK, tok0 = m0 - b0i * NTOK;
        int m1 = m0 + 8;
        int b1i = m1 / NTOK, tok1 = m1 - b1i * NTOK;
        #pragma unroll
        for (int ni = 0; ni < 4; ni++) {
            int col0 = bn + wn + ni * 8 + qc * 2;
            #pragma unroll
            for (int e = 0; e < 2; e++) {
                int col = col0 + e;
                float bb = bias[col], gg = bng[col], be = bnb[col];
                float v0 = fmaxf(d[mi][ni][e] + bb, 0.f) * inv_bn * gg + be;
                float v1 = fmaxf(d[mi][ni][2 + e] + bb, 0.f) * inv_bn * gg + be;
                Cc[((size_t)b0i * C_ + col) * NTOK + tok0] = v0;
                Cc[((size_t)b1i * C_ + col) * NTOK + tok1] = v1;
            }
        }
    }
}

// ---------------------------------------------------------------------------
// Tensor-core flash attention (tf32 mma), batched x2. Grid: (13, 32, 2).
// Fragment loads via ldmatrix.x2; Ks stores STS.128; Vt transpose store
// remapped (quad-per-row) from 8-way to 2-way bank conflicts.
// ---------------------------------------------------------------------------
struct AttnRegs {
    uint32_t aQ[2][8][4];
    float o[2][8][4];
    float l[2][2];
};

template<int NTL>
__device__ __forceinline__ void attn_tile(
    AttnRegs& R, const uint32_t (*Ks)[68], const uint32_t (*Vt)[68],
    int qr, int qc, int lane)
{
    int owner_lo = (lane & ~3) | (qc >> 1);
    int owner_hi = owner_lo + 2;
    int odd = qc & 1;
    int b_row  = lane & 7;
    int b_koff = ((lane >> 3) & 1) * 4;

    #pragma unroll
    for (int nt = 0; nt < NTL; nt++) {
        float s[2][4];
        #pragma unroll
        for (int mt = 0; mt < 2; mt++)
            #pragma unroll
            for (int e = 0; e < 4; e++) s[mt][e] = 0.f;

        uint32_t bK[8][2];
        #pragma unroll
        for (int ks = 0; ks < 8; ks++) {
            uint32_t ad = smem_u32(&Ks[nt * 8 + b_row][ks * 8 + b_koff]);
            ldsm_x2(bK[ks][0], bK[ks][1], ad);
        }
        #pragma unroll
        for (int mt = 0; mt < 2; mt++)
            #pragma unroll
            for (int ks = 0; ks < 8; ks++)
                mma_tf32(s[mt], R.aQ[mt][ks], bK[ks]);

        #pragma unroll
        for (int mt = 0; mt < 2; mt++) {
            float p0 = __expf(s[mt][0] * 0.125f);
            float p1 = __expf(s[mt][1] * 0.125f);
            float p2 = __expf(s[mt][2] * 0.125f);
            float p3 = __expf(s[mt][3] * 0.125f);
            R.l[mt][0] += p0 + p1;
            R.l[mt][1] += p2 + p3;
            s[mt][0] = __uint_as_float(f2tf32(p0));
            s[mt][1] = __uint_as_float(f2tf32(p1));
            s[mt][2] = __uint_as_float(f2tf32(p2));
            s[mt][3] = __uint_as_float(f2tf32(p3));
        }

        uint32_t aP[2][4];
        #pragma unroll
        for (int mt = 0; mt < 2; mt++) {
            float t00 = __shfl_sync(0xffffffffu, s[mt][0], owner_lo);
            float t01 = __shfl_sync(0xffffffffu, s[mt][1], owner_lo);
            float t10 = __shfl_sync(0xffffffffu, s[mt][2], owner_lo);
            float t11 = __shfl_sync(0xffffffffu, s[mt][3], owner_lo);
            float u00 = __shfl_sync(0xffffffffu, s[mt][0], owner_hi);
            float u01 = __shfl_sync(0xffffffffu, s[mt][1], owner_hi);
            float u10 = __shfl_sync(0xffffffffu, s[mt][2], owner_hi);
            float u11 = __shfl_sync(0xffffffffu, s[mt][3], owner_hi);
            aP[mt][0] = __float_as_uint(odd ? t01 : t00);
            aP[mt][1] = __float_as_uint(odd ? t11 : t10);
            aP[mt][2] = __float_as_uint(odd ? u01 : u00);
            aP[mt][3] = __float_as_uint(odd ? u11 : u10);
        }

        #pragma unroll
        for (int ntd = 0; ntd < 8; ntd++) {
            uint32_t bV[2];
            uint32_t ad = smem_u32(&Vt[ntd * 8 + b_row][nt * 8 + b_koff]);
            ldsm_x2(bV[0], bV[1], ad);
            mma_tf32(R.o[0][ntd], aP[0], bV);
            mma_tf32(R.o[1][ntd], aP[1], bV);
        }
    }
}

__global__ __launch_bounds__(128, 2) void attn_mma_kernel(A2 p) {
    int gz = blockIdx.z;
    int bh = blockIdx.y;
    int b = bh >> 3, h = bh & 7;
    int wid = threadIdx.x >> 5, lane = threadIdx.x & 31;
    int qr = lane >> 2, qc = lane & 3;
    int q0 = blockIdx.x * 128 + wid * 32;

    __shared__ __align__(16) uint32_t Ks[64][68];
    __shared__ __align__(16) uint32_t Vt[64][68];

    const float* Qb = p.Q[gz] + (size_t)b * NTOK * C_ + h * HD;
    const float* Kb = p.K[gz] + (size_t)b * NTOK * C_ + h * HD;
    const float* Vb = p.V[gz] + (size_t)b * NTOK * C_ + h * HD;

    AttnRegs R;
    #pragma unroll
    for (int mt = 0; mt < 2; mt++) {
        int r0 = q0 + mt * 16 + qr;
        int r1 = r0 + 8;
        int rr0 = r0 < NTOK ? r0 : NTOK - 1;
        int rr1 = r1 < NTOK ? r1 : NTOK - 1;
        #pragma unroll
        for (int ks = 0; ks < 8; ks++) {
            int c = ks * 8 + qc;
            R.aQ[mt][ks][0] = f2tf32(Qb[(size_t)rr0 * C_ + c]);
            R.aQ[mt][ks][1] = f2tf32(Qb[(size_t)rr1 * C_ + c]);
            R.aQ[mt][ks][2] = f2tf32(Qb[(size_t)rr0 * C_ + c + 4]);
            R.aQ[mt][ks][3] = f2tf32(Qb[(size_t)rr1 * C_ + c + 4]);
        }
    }
    #pragma unroll
    for (int mt = 0; mt < 2; mt++) {
        #pragma unroll
        for (int nt = 0; nt < 8; nt++)
            #pragma unroll
            for (int e = 0; e < 4; e++) R.o[mt][nt][e] = 0.f;
        R.l[mt][0] = 0.f; R.l[mt][1] = 0.f;
    }

    // V-loader lane roles (quad-per-row mapping, 2-way store conflicts)
    int vq = threadIdx.x & 3;
    int vr = (threadIdx.x >> 2) & 7;
    int vh = threadIdx.x >> 5;

    // 24 full 64-key tiles + one 32-key tail (1568 = 24*64 + 32)
    for (int kt = 0; kt < 25; kt++) {
        int kbase = kt * 64;
        int nk = (kt == 24) ? 32 : 64;
        if (kt > 0) __syncthreads();
        // K tile: coalesced float4 load, STS.128 store
        for (int idx = threadIdx.x; idx < nk * 16; idx += 128) {
            int row = idx >> 4;
            int c4 = (idx & 15) * 4;
            float4 kv = *(const float4*)(Kb + (size_t)(kbase + row) * C_ + c4);
            *(uint4*)&Ks[row][c4] =
                make_uint4(f2tf32(kv.x), f2tf32(kv.y), f2tf32(kv.z), f2tf32(kv.w));
        }
        // V tile: transposed store, remapped lanes
        #pragma unroll
        for (int it = 0; it < 8; it++) {
            int row = vh * 8 + vr + (it & 1) * 32;
            if (row < nk) {
                int c4 = vq * 4 + (it >> 1) * 16;
                float4 vv = *(const float4*)(Vb + (size_t)(kbase + row) * C_ + c4);
                Vt[c4 + 0][row] = f2tf32(vv.x);
                Vt[c4 + 1][row] = f2tf32(vv.y);
                Vt[c4 + 2][row] = f2tf32(vv.z);
                Vt[c4 + 3][row] = f2tf32(vv.w);
            }
        }
        __syncthreads();
        if (nk == 64) attn_tile<8>(R, Ks, Vt, qr, qc, lane);
        else          attn_tile<4>(R, Ks, Vt, qr, qc, lane);
    }

    // Finalize: quad-reduce row sums, normalize, residual-add store
    float* Tb = p.T[gz] + (size_t)b * NTOK * C_ + h * HD;
    #pragma unroll
    for (int mt = 0; mt < 2; mt++) {
        float l0 = R.l[mt][0];
        l0 += __shfl_xor_sync(0xffffffffu, l0, 1);
        l0 += __shfl_xor_sync(0xffffffffu, l0, 2);
        float l1 = R.l[mt][1];
        l1 += __shfl_xor_sync(0xffffffffu, l1, 1);
        l1 += __shfl_xor_sync(0xffffffffu, l1, 2);
        float inv0 = 1.f / l0, inv1 = 1.f / l1;
        int r0 = q0 + mt * 16 + qr;
        int r1 = r0 + 8;
        #pragma unroll
        for (int ntd = 0; ntd < 8; ntd++) {
            int col = ntd * 8 + qc * 2;
            if (r0 < NTOK) {
                float2* pp = (float2*)(Tb + (size_t)r0 * C_ + col);
                float2 old = *pp;
                old.x += R.o[mt][ntd][0] * inv0;
                old.y += R.o[mt][ntd][1] * inv0;
                *pp = old;
            }
            if (r1 < NTOK) {
                float2* pp = (float2*)(Tb + (size_t)r1 * C_ + col);
                float2 old = *pp;
                old.x += R.o[mt][ntd][2] * inv1;
                old.y += R.o[mt][ntd][3] * inv1;
                *pp = old;
            }
        }
    }
}

// ---------------------------------------------------------------------------
// Host launcher
// ---------------------------------------------------------------------------
extern "C" void kernel_launch(void* const* d_in, const int* in_sizes, int n_in,
                              void* d_out, int out_size) {
    const float* x1    = (const float*)d_in[0];
    const float* x2    = (const float*)d_in[1];
    const float* Wq1   = (const float*)d_in[2];
    const float* bq1   = (const float*)d_in[3];
    const float* Wk1   = (const float*)d_in[4];
    const float* bk1   = (const float*)d_in[5];
    const float* Wv1   = (const float*)d_in[6];
    const float* bv1   = (const float*)d_in[7];
    const float* ln1_g = (const float*)d_in[8];
    const float* ln1_b = (const float*)d_in[9];
    const float* Wq2   = (const float*)d_in[10];
    const float* bq2   = (const float*)d_in[11];
    const float* Wk2   = (const float*)d_in[12];
    const float* bk2   = (const float*)d_in[13];
    const float* Wv2   = (const float*)d_in[14];
    const float* bv2   = (const float*)d_in[15];
    const float* ln2_g = (const float*)d_in[16];
    const float* ln2_b = (const float*)d_in[17];
    const float* o1w   = (const float*)d_in[18];
    const float* o1b   = (const float*)d_in[19];
    const float* bn1g  = (const float*)d_in[20];
    const float* bn1b  = (const float*)d_in[21];
    const float* o2w   = (const float*)d_in[22];
    const float* o2b   = (const float*)d_in[23];
    const float* bn2g  = (const float*)d_in[24];
    const float* bn2b  = (const float*)d_in[25];
    float* out = (float*)d_out;

    float* S = nullptr;
    cudaGetSymbolAddress((void**)&S, g_scratch);
    const size_t SZ = (size_t)M_ALL * C_;
    float* t1  = S + 0 * SZ;
    float* t2  = S + 1 * SZ;
    float* ln1 = S + 2 * SZ;
    float* ln2 = S + 3 * SZ;
    float* q1  = S + 4 * SZ;
    float* k1  = S + 5 * SZ;
    float* v1  = S + 6 * SZ;
    float* q2  = S + 7 * SZ;
    float* k2  = S + 8 * SZ;
    float* v2  = S + 9 * SZ;

    dim3 tokg(NTOK / 32, C_ / 32, B_), tokb(32, 8);
    tok_kernel<<<tokg, tokb>>>(x1, t1);
    tok_kernel<<<tokg, tokb>>>(x2, t2);

    dim3 lng(M_ALL, 2);
    dim3 gg(C_ / 128, M_ALL / 128, 6);   // (4, 49, 6)
    dim3 og(C_ / 128, M_ALL / 128, 2);   // (4, 49, 2)
    dim3 ag(13, B_ * NH, 2);             // (13, 32, 2)

    for (int i = 0; i < 3; i++) {
        size_t wo = (size_t)i * C_ * C_;
        size_t bo = (size_t)i * C_;

        L2 lp;
        lp.X[0] = t1; lp.g[0] = ln1_g + bo; lp.b[0] = ln1_b + bo; lp.Y[0] = ln1;
        lp.X[1] = t2; lp.g[1] = ln2_g + bo; lp.b[1] = ln2_b + bo; lp.Y[1] = ln2;
        ln_kernel<<<lng, 128>>>(lp);

        P6 gp;
        gp.A[0] = ln1; gp.W[0] = Wq1 + wo; gp.bs[0] = bq1 + bo; gp.C[0] = q1;
        gp.A[1] = t2;  gp.W[1] = Wk1 + wo; gp.bs[1] = bk1 + bo; gp.C[1] = k1;
        gp.A[2] = t2;  gp.W[2] = Wv1 + wo; gp.bs[2] = bv1 + bo; gp.C[2] = v1;
        gp.A[3] = ln2; gp.W[3] = Wq2 + wo; gp.bs[3] = bq2 + bo; gp.C[3] = q2;
        gp.A[4] = t1;  gp.W[4] = Wk2 + wo; gp.bs[4] = bk2 + bo; gp.C[4] = k2;
        gp.A[5] = t1;  gp.W[5] = Wv2 + wo; gp.bs[5] = bv2 + bo; gp.C[5] = v2;
        gemm_proj_kernel<<<gg, 256>>>(gp);

        A2 ap;
        ap.Q[0] = q1; ap.K[0] = k1; ap.V[0] = v1; ap.T[0] = t1;
        ap.Q[1] = q2; ap.K[1] = k2; ap.V[1] = v2; ap.T[1] = t2;
        attn_mma_kernel<<<ag, 128>>>(ap);
    }

    P2 op;
    op.A[0] = t1; op.W[0] = o1w; op.bs[0] = o1b; op.g[0] = bn1g; op.be[0] = bn1b;
    op.C[0] = out;
    op.A[1] = t2; op.W[1] = o2w; op.bs[1] = o2b; op.g[1] = bn2g; op.be[1] = bn2b;
    op.C[1] = out + (size_t)B_ * C_ * NTOK;
    gemm_out_kernel<<<og, 256>>>(op);

    (void)in_sizes; (void)n_in; (void)out_size;
}